// round 10
// baseline (speedup 1.0000x reference)
#include <cuda_runtime.h>

#define N_NODES 100000
#define N_EDGES 1600000
#define C 128
#define NG 128
#define LSLOPE 0.01f
#define FULL 0xffffffffu

// ---------------- scratch (device globals: no allocation allowed) ----------
__device__ __align__(32) float g_B1[(size_t)N_NODES * C];   // H (kept in L2 via evict_last loads)
__device__ __align__(16) float g_B2[(size_t)N_NODES * C];   // AGG / layer input
__device__ int   g_deg_i[N_NODES];
__device__ float g_dinv[N_NODES];
__device__ int   g_off[N_NODES + 1];       // CSR offsets (by dst)
__device__ int   g_cursor[N_NODES];        // fill cursors
__device__ int   g_esrc[N_EDGES];          // src per CSR slot
__device__ float g_enorm[N_EDGES];         // dinv[s]*dinv[d] per CSR slot
__device__ __align__(16) float g_sums[NG * C];
__device__ float g_cnts[NG];

__device__ __forceinline__ float lrelu(float v) { return v > 0.f ? v : LSLOPE * v; }

// 32-byte L2::evict_last gather (8 floats) — the only form ptxas accepts on sm_103a
__device__ __forceinline__ void ldg32_keep(const float* p, float* out8) {
    unsigned long long r0, r1, r2, r3;
    asm volatile("ld.global.L2::evict_last.v4.b64 {%0,%1,%2,%3}, [%4];"
                 : "=l"(r0), "=l"(r1), "=l"(r2), "=l"(r3) : "l"(p));
    out8[0] = __uint_as_float((unsigned)r0); out8[1] = __uint_as_float((unsigned)(r0 >> 32));
    out8[2] = __uint_as_float((unsigned)r1); out8[3] = __uint_as_float((unsigned)(r1 >> 32));
    out8[4] = __uint_as_float((unsigned)r2); out8[5] = __uint_as_float((unsigned)(r2 >> 32));
    out8[6] = __uint_as_float((unsigned)r3); out8[7] = __uint_as_float((unsigned)(r3 >> 32));
}

// ---------------- prep: zero accumulators ----------------------------------
__global__ void zero_prep_kernel() {
    int i = blockIdx.x * blockDim.x + threadIdx.x;
    if (i < N_NODES) g_deg_i[i] = 0;
    if (i < NG * C)  g_sums[i] = 0.f;
    if (i < NG)      g_cnts[i] = 0.f;
}

// ---------------- degree histogram + graph counts ----------------------------
__global__ void deg_kernel(const int* __restrict__ ei, const int* __restrict__ batch) {
    int e = blockIdx.x * blockDim.x + threadIdx.x;
    if (e < N_EDGES) {
        unsigned d = (unsigned)ei[N_EDGES + e];
        if (d < N_NODES) atomicAdd(&g_deg_i[d], 1);
    }
    if (e < N_NODES) {
        unsigned g = (unsigned)batch[e];
        if (g < NG) atomicAdd(&g_cnts[g], 1.0f);
    }
}

// ---------------- single-block scan: offsets, cursors, dinv -----------------
__global__ __launch_bounds__(1024)
void scan_kernel() {
    __shared__ int part[1024];
    const int CHUNK = (N_NODES + 1023) / 1024;   // 98
    int t = threadIdx.x;
    int start = t * CHUNK;
    int end = min(start + CHUNK, N_NODES);

    int s = 0;
    for (int i = start; i < end; i++) s += g_deg_i[i];
    part[t] = s;
    __syncthreads();

    for (int off = 1; off < 1024; off <<= 1) {
        int v = (t >= off) ? part[t - off] : 0;
        __syncthreads();
        part[t] += v;
        __syncthreads();
    }

    int running = part[t] - s;   // exclusive base for this chunk
    for (int i = start; i < end; i++) {
        g_off[i] = running;
        g_cursor[i] = running;
        int d = g_deg_i[i];
        running += d;
        g_dinv[i] = rsqrtf((float)d + 1.0f);
    }
    if (t == 1023) g_off[N_NODES] = running;
}

// ---------------- CSR fill: permute edges by dst -----------------------------
__global__ void fill_kernel(const int* __restrict__ ei) {
    int e = blockIdx.x * blockDim.x + threadIdx.x;
    if (e >= N_EDGES) return;
    unsigned s = (unsigned)ei[e];
    unsigned d = (unsigned)ei[N_EDGES + e];
    if (s >= N_NODES || d >= N_NODES) return;
    int pos = atomicAdd(&g_cursor[d], 1);
    g_esrc[pos]  = (int)s;
    g_enorm[pos] = g_dinv[s] * g_dinv[d];
}

// ---------------- fused GEMM (R5 shape): H=act(X)@W -> B1 ; AGG=H*d2 -> B2 --
template <bool TRANSFORM>
__global__ __launch_bounds__(256)
void gemm_kernel(const float* __restrict__ Xext, const float* __restrict__ W,
                 const float* __restrict__ bin)
{
    __shared__ float  Xs[32][33];
    __shared__ float4 Ws4[32][32];   // [kk][col/4]

    const float* __restrict__ X = TRANSFORM ? (const float*)g_B2 : Xext;

    int tid  = threadIdx.x;
    int row0 = blockIdx.x * 32;
    int tx   = tid & 31;
    int ty   = tid >> 5;

    float acc[4][4];
#pragma unroll
    for (int i = 0; i < 4; i++)
#pragma unroll
        for (int j = 0; j < 4; j++) acc[i][j] = 0.f;

    for (int kt = 0; kt < 4; ++kt) {
        {
            int r = tid >> 3;
            int c = (tid & 7) * 4;
            int kcol = kt * 32 + c;
            float4 v = *(const float4*)(X + (size_t)(row0 + r) * C + kcol);
            if (TRANSFORM) {
                v.x = lrelu(v.x + bin[kcol + 0]);
                v.y = lrelu(v.y + bin[kcol + 1]);
                v.z = lrelu(v.z + bin[kcol + 2]);
                v.w = lrelu(v.w + bin[kcol + 3]);
            }
            Xs[r][c + 0] = v.x; Xs[r][c + 1] = v.y;
            Xs[r][c + 2] = v.z; Xs[r][c + 3] = v.w;
        }
#pragma unroll
        for (int i = 0; i < 4; i++) {
            int idx = tid + i * 256;
            int kk  = idx >> 5;
            int c4  = idx & 31;
            Ws4[kk][c4] = *(const float4*)(W + (size_t)(kt * 32 + kk) * C + c4 * 4);
        }
        __syncthreads();

#pragma unroll
        for (int kk = 0; kk < 32; ++kk) {
            float x0 = Xs[ty * 4 + 0][kk];
            float x1 = Xs[ty * 4 + 1][kk];
            float x2 = Xs[ty * 4 + 2][kk];
            float x3 = Xs[ty * 4 + 3][kk];
            float4 w = Ws4[kk][tx];
            acc[0][0] += x0 * w.x; acc[0][1] += x0 * w.y; acc[0][2] += x0 * w.z; acc[0][3] += x0 * w.w;
            acc[1][0] += x1 * w.x; acc[1][1] += x1 * w.y; acc[1][2] += x1 * w.z; acc[1][3] += x1 * w.w;
            acc[2][0] += x2 * w.x; acc[2][1] += x2 * w.y; acc[2][2] += x2 * w.z; acc[2][3] += x2 * w.w;
            acc[3][0] += x3 * w.x; acc[3][1] += x3 * w.y; acc[3][2] += x3 * w.z; acc[3][3] += x3 * w.w;
        }
        __syncthreads();
    }

#pragma unroll
    for (int i = 0; i < 4; i++) {
        int r = row0 + ty * 4 + i;
        float d  = g_dinv[r];
        float d2 = d * d;
        float4 h = make_float4(acc[i][0], acc[i][1], acc[i][2], acc[i][3]);
        *(float4*)(g_B1 + (size_t)r * C + tx * 4) = h;
        float4 a = make_float4(h.x * d2, h.y * d2, h.z * d2, h.w * d2);
        *(float4*)(g_B2 + (size_t)r * C + tx * 4) = a;
    }
}

// ---------------- aggregation v4: half-warp edges, 32B evict_last gathers ----
// Warp per dst node. Lanes 0-15 process even CSR slots, 16-31 odd slots; each
// lane owns 8 channels (32 B) -> one v4.b64 gather per edge per lane. Halves
// are merged with shfl_xor(16) and lanes 0-15 write the row.
// POOL=false: B2[node] += AGG          (layer 1)
// POOL=true : sums[batch[node]] += lrelu(AGG + B2self + b2)   (layer 2 + pool)
template <bool POOL>
__global__ __launch_bounds__(256)
void agg_kernel(const int* __restrict__ batch, const float* __restrict__ b2)
{
    int node = (blockIdx.x * blockDim.x + threadIdx.x) >> 5;
    int lane = threadIdx.x & 31;
    if (node >= N_NODES) return;

    int half = lane >> 4;            // 0: even slots, 1: odd slots
    int c8   = (lane & 15) * 8;      // channel base (8 floats)

    int beg = g_off[node];
    int end = g_off[node + 1];

    float a[8] = {0.f, 0.f, 0.f, 0.f, 0.f, 0.f, 0.f, 0.f};
    float v0[8], v1[8];

    int i = beg + half;
    // 2 edges in flight per half-warp (4 per warp)
    for (; i + 2 < end; i += 4) {
        int   s0 = g_esrc[i];
        int   s1 = g_esrc[i + 2];
        float n0 = g_enorm[i];
        float n1 = g_enorm[i + 2];
        ldg32_keep(g_B1 + (size_t)s0 * C + c8, v0);
        ldg32_keep(g_B1 + (size_t)s1 * C + c8, v1);
#pragma unroll
        for (int k = 0; k < 8; k++) a[k] += v0[k] * n0 + v1[k] * n1;
    }
    for (; i < end; i += 2) {
        int   s0 = g_esrc[i];
        float n0 = g_enorm[i];
        ldg32_keep(g_B1 + (size_t)s0 * C + c8, v0);
#pragma unroll
        for (int k = 0; k < 8; k++) a[k] += v0[k] * n0;
    }

    // merge odd half into even half
#pragma unroll
    for (int k = 0; k < 8; k++) a[k] += __shfl_xor_sync(FULL, a[k], 16);

    if (half == 0) {
        float* p = g_B2 + (size_t)node * C + c8;     // holds self-loop term
        float4 u0 = *(const float4*)p;
        float4 u1 = *(const float4*)(p + 4);
        u0.x += a[0]; u0.y += a[1]; u0.z += a[2]; u0.w += a[3];
        u1.x += a[4]; u1.y += a[5]; u1.z += a[6]; u1.w += a[7];

        if (!POOL) {
            *(float4*)p       = u0;
            *(float4*)(p + 4) = u1;
        } else {
            unsigned g = (unsigned)batch[node];
            if (g >= NG) return;
            const float* bb = b2 + c8;
            float* q = g_sums + g * C + c8;
            atomicAdd(q + 0, lrelu(u0.x + bb[0]));
            atomicAdd(q + 1, lrelu(u0.y + bb[1]));
            atomicAdd(q + 2, lrelu(u0.z + bb[2]));
            atomicAdd(q + 3, lrelu(u0.w + bb[3]));
            atomicAdd(q + 4, lrelu(u1.x + bb[4]));
            atomicAdd(q + 5, lrelu(u1.y + bb[5]));
            atomicAdd(q + 6, lrelu(u1.z + bb[6]));
            atomicAdd(q + 7, lrelu(u1.w + bb[7]));
        }
    }
}

// ---------------- MLP head ---------------------------------------------------
__global__ __launch_bounds__(128)
void head_kernel(const float* __restrict__ W3, const float* __restrict__ b3,
                 const float* __restrict__ W4, const float* __restrict__ b4,
                 const float* __restrict__ W5, const float* __restrict__ b5,
                 float* __restrict__ out)
{
    int g = blockIdx.x;
    int t = threadIdx.x;
    __shared__ float gv[128], t1[64], t2[64];

    float inv = 1.0f / fmaxf(g_cnts[g], 1.0f);
    gv[t] = g_sums[g * C + t] * inv;
    __syncthreads();

    if (t < 64) {
        float s = b3[t];
#pragma unroll 8
        for (int k = 0; k < 128; k++) s += gv[k] * W3[k * 64 + t];
        t1[t] = lrelu(s);
    }
    __syncthreads();
    if (t < 64) {
        float s = b4[t];
#pragma unroll 8
        for (int k = 0; k < 64; k++) s += t1[k] * W4[k * 64 + t];
        t2[t] = lrelu(s);
    }
    __syncthreads();
    if (t < 10) {
        float s = b5[t];
#pragma unroll 8
        for (int k = 0; k < 64; k++) s += t2[k] * W5[k * 10 + t];
        out[g * 10 + t] = s;
    }
}

// ---------------- launch ----------------------------------------------------
// Inputs resolved by ELEMENT COUNT (ordering-agnostic). edge_index/batch are
// int32 (JAX x64 disabled downcasts int64 -> int32).
extern "C" void kernel_launch(void* const* d_in, const int* in_sizes, int n_in,
                              void* d_out, int out_size)
{
    const float* x = nullptr;
    const int* ei = nullptr;
    const int* batch = nullptr;
    const float *W1 = nullptr, *b1 = nullptr, *W2 = nullptr, *b2 = nullptr;
    const float *W3 = nullptr, *b3 = nullptr, *W4 = nullptr, *b4 = nullptr;
    const float *W5 = nullptr, *b5 = nullptr;

    for (int i = 0; i < n_in; i++) {
        const void* p = d_in[i];
        switch (in_sizes[i]) {
            case 12800000: x = (const float*)p; break;
            case 3200000:  ei = (const int*)p; break;
            case 100000:   batch = (const int*)p; break;
            case 16384:    if (!W1) W1 = (const float*)p; else W2 = (const float*)p; break;
            case 8192:     W3 = (const float*)p; break;
            case 4096:     W4 = (const float*)p; break;
            case 640:      W5 = (const float*)p; break;
            case 128:      if (!b1) b1 = (const float*)p; else b2 = (const float*)p; break;
            case 64:       if (!b3) b3 = (const float*)p; else b4 = (const float*)p; break;
            case 10:       b5 = (const float*)p; break;
            default: break;
        }
    }
    float* out = (float*)d_out;
    (void)out_size;

    // CSR build (once, reused by both layers)
    zero_prep_kernel<<<(N_NODES + 255) / 256, 256>>>();
    deg_kernel<<<(N_EDGES + 255) / 256, 256>>>(ei, batch);
    scan_kernel<<<1, 1024>>>();
    fill_kernel<<<(N_EDGES + 255) / 256, 256>>>(ei);

    // layer 1
    gemm_kernel<false><<<N_NODES / 32, 256>>>(x, W1, nullptr);
    agg_kernel<false><<<(N_NODES * 32 + 255) / 256, 256>>>(batch, b2);

    // layer 2 (pool fused into agg)
    gemm_kernel<true><<<N_NODES / 32, 256>>>(nullptr, W2, b1);
    agg_kernel<true><<<(N_NODES * 32 + 255) / 256, 256>>>(batch, b2);

    // MLP head
    head_kernel<<<NG, 128>>>(W3, b3, W4, b4, W5, b5, out);
}

// round 11
// speedup vs baseline: 1.1536x; 1.1536x over previous
#include <cuda_runtime.h>
#include <cuda_fp16.h>

#define N_NODES 100000
#define N_EDGES 1600000
#define C 128
#define NG 128
#define LSLOPE 0.01f
#define FULL 0xffffffffu

// ---------------- scratch (device globals: no allocation allowed) ----------
__device__ __align__(16) __half g_B1h[(size_t)N_NODES * C];  // H in fp16 (25.6 MB, gathered)
__device__ __align__(16) float  g_B2[(size_t)N_NODES * C];   // AGG / layer input (fp32)
__device__ int   g_deg_i[N_NODES];
__device__ float g_dinv[N_NODES];
__device__ int   g_off[N_NODES + 1];       // CSR offsets (by dst)
__device__ int   g_cursor[N_NODES];        // fill cursors
__device__ int   g_esrc[N_EDGES];          // src per CSR slot
__device__ float g_enorm[N_EDGES];         // dinv[s]*dinv[d] per CSR slot
__device__ __align__(16) float g_sums[NG * C];
__device__ float g_cnts[NG];

__device__ __forceinline__ float lrelu(float v) { return v > 0.f ? v : LSLOPE * v; }

// ---------------- prep: zero accumulators ----------------------------------
__global__ void zero_prep_kernel() {
    int i = blockIdx.x * blockDim.x + threadIdx.x;
    if (i < N_NODES) g_deg_i[i] = 0;
    if (i < NG * C)  g_sums[i] = 0.f;
    if (i < NG)      g_cnts[i] = 0.f;
}

// ---------------- degree histogram + graph counts ----------------------------
__global__ void deg_kernel(const int* __restrict__ ei, const int* __restrict__ batch) {
    int e = blockIdx.x * blockDim.x + threadIdx.x;
    if (e < N_EDGES) {
        unsigned d = (unsigned)ei[N_EDGES + e];
        if (d < N_NODES) atomicAdd(&g_deg_i[d], 1);
    }
    if (e < N_NODES) {
        unsigned g = (unsigned)batch[e];
        if (g < NG) atomicAdd(&g_cnts[g], 1.0f);
    }
}

// ---------------- single-block scan: offsets, cursors, dinv -----------------
__global__ __launch_bounds__(1024)
void scan_kernel() {
    __shared__ int part[1024];
    const int CHUNK = (N_NODES + 1023) / 1024;   // 98
    int t = threadIdx.x;
    int start = t * CHUNK;
    int end = min(start + CHUNK, N_NODES);

    int s = 0;
    for (int i = start; i < end; i++) s += g_deg_i[i];
    part[t] = s;
    __syncthreads();

    for (int off = 1; off < 1024; off <<= 1) {
        int v = (t >= off) ? part[t - off] : 0;
        __syncthreads();
        part[t] += v;
        __syncthreads();
    }

    int running = part[t] - s;   // exclusive base for this chunk
    for (int i = start; i < end; i++) {
        g_off[i] = running;
        g_cursor[i] = running;
        int d = g_deg_i[i];
        running += d;
        g_dinv[i] = rsqrtf((float)d + 1.0f);
    }
    if (t == 1023) g_off[N_NODES] = running;
}

// ---------------- CSR fill: permute edges by dst -----------------------------
__global__ void fill_kernel(const int* __restrict__ ei) {
    int e = blockIdx.x * blockDim.x + threadIdx.x;
    if (e >= N_EDGES) return;
    unsigned s = (unsigned)ei[e];
    unsigned d = (unsigned)ei[N_EDGES + e];
    if (s >= N_NODES || d >= N_NODES) return;
    int pos = atomicAdd(&g_cursor[d], 1);
    g_esrc[pos]  = (int)s;
    g_enorm[pos] = g_dinv[s] * g_dinv[d];
}

// ---------------- fused GEMM (R5 shape): H=act(X)@W -> B1h(fp16) ; AGG -> B2 -
template <bool TRANSFORM>
__global__ __launch_bounds__(256)
void gemm_kernel(const float* __restrict__ Xext, const float* __restrict__ W,
                 const float* __restrict__ bin)
{
    __shared__ float  Xs[32][33];
    __shared__ float4 Ws4[32][32];   // [kk][col/4]

    const float* __restrict__ X = TRANSFORM ? (const float*)g_B2 : Xext;

    int tid  = threadIdx.x;
    int row0 = blockIdx.x * 32;
    int tx   = tid & 31;
    int ty   = tid >> 5;

    float acc[4][4];
#pragma unroll
    for (int i = 0; i < 4; i++)
#pragma unroll
        for (int j = 0; j < 4; j++) acc[i][j] = 0.f;

    for (int kt = 0; kt < 4; ++kt) {
        {
            int r = tid >> 3;
            int c = (tid & 7) * 4;
            int kcol = kt * 32 + c;
            float4 v = *(const float4*)(X + (size_t)(row0 + r) * C + kcol);
            if (TRANSFORM) {
                v.x = lrelu(v.x + bin[kcol + 0]);
                v.y = lrelu(v.y + bin[kcol + 1]);
                v.z = lrelu(v.z + bin[kcol + 2]);
                v.w = lrelu(v.w + bin[kcol + 3]);
            }
            Xs[r][c + 0] = v.x; Xs[r][c + 1] = v.y;
            Xs[r][c + 2] = v.z; Xs[r][c + 3] = v.w;
        }
#pragma unroll
        for (int i = 0; i < 4; i++) {
            int idx = tid + i * 256;
            int kk  = idx >> 5;
            int c4  = idx & 31;
            Ws4[kk][c4] = *(const float4*)(W + (size_t)(kt * 32 + kk) * C + c4 * 4);
        }
        __syncthreads();

#pragma unroll
        for (int kk = 0; kk < 32; ++kk) {
            float x0 = Xs[ty * 4 + 0][kk];
            float x1 = Xs[ty * 4 + 1][kk];
            float x2 = Xs[ty * 4 + 2][kk];
            float x3 = Xs[ty * 4 + 3][kk];
            float4 w = Ws4[kk][tx];
            acc[0][0] += x0 * w.x; acc[0][1] += x0 * w.y; acc[0][2] += x0 * w.z; acc[0][3] += x0 * w.w;
            acc[1][0] += x1 * w.x; acc[1][1] += x1 * w.y; acc[1][2] += x1 * w.z; acc[1][3] += x1 * w.w;
            acc[2][0] += x2 * w.x; acc[2][1] += x2 * w.y; acc[2][2] += x2 * w.z; acc[2][3] += x2 * w.w;
            acc[3][0] += x3 * w.x; acc[3][1] += x3 * w.y; acc[3][2] += x3 * w.z; acc[3][3] += x3 * w.w;
        }
        __syncthreads();
    }

#pragma unroll
    for (int i = 0; i < 4; i++) {
        int r = row0 + ty * 4 + i;
        float d  = g_dinv[r];
        float d2 = d * d;
        // fp16 H (gathered by agg)
        __half2 h01 = __floats2half2_rn(acc[i][0], acc[i][1]);
        __half2 h23 = __floats2half2_rn(acc[i][2], acc[i][3]);
        uint2 packed = make_uint2(*(unsigned*)&h01, *(unsigned*)&h23);
        *(uint2*)(g_B1h + (size_t)r * C + tx * 4) = packed;
        // fp32 self-loop term
        float4 a = make_float4(acc[i][0] * d2, acc[i][1] * d2, acc[i][2] * d2, acc[i][3] * d2);
        *(float4*)(g_B2 + (size_t)r * C + tx * 4) = a;
    }
}

// ---------------- aggregation: half-warp edges, 16B fp16 gathers -------------
// Warp per dst node. Lanes 0-15: even CSR slots, 16-31: odd slots. Each lane
// owns 8 channels -> one uint4 (8 halves) per edge. Merge halves via shfl_xor.
// POOL=false: B2[node] += AGG                              (layer 1)
// POOL=true : sums[batch[node]] += lrelu(AGG + B2self + b2) (layer 2 + pool)
template <bool POOL>
__global__ __launch_bounds__(256)
void agg_kernel(const int* __restrict__ batch, const float* __restrict__ b2)
{
    int node = (blockIdx.x * blockDim.x + threadIdx.x) >> 5;
    int lane = threadIdx.x & 31;
    if (node >= N_NODES) return;

    int half = lane >> 4;            // 0: even slots, 1: odd slots
    int c8   = (lane & 15) * 8;      // channel base (8 channels, 16 bytes fp16)

    int beg = g_off[node];
    int end = g_off[node + 1];

    float a[8] = {0.f, 0.f, 0.f, 0.f, 0.f, 0.f, 0.f, 0.f};

    int i = beg + half;
    for (; i + 2 < end; i += 4) {          // 2 edges in flight per half-warp
        int   s0 = g_esrc[i];
        int   s1 = g_esrc[i + 2];
        float n0 = g_enorm[i];
        float n1 = g_enorm[i + 2];
        uint4 u0 = *(const uint4*)(g_B1h + (size_t)s0 * C + c8);
        uint4 u1 = *(const uint4*)(g_B1h + (size_t)s1 * C + c8);
        const __half2* h0 = (const __half2*)&u0;
        const __half2* h1 = (const __half2*)&u1;
#pragma unroll
        for (int k = 0; k < 4; k++) {
            float2 f0 = __half22float2(h0[k]);
            float2 f1 = __half22float2(h1[k]);
            a[2 * k + 0] += f0.x * n0 + f1.x * n1;
            a[2 * k + 1] += f0.y * n0 + f1.y * n1;
        }
    }
    for (; i < end; i += 2) {
        int   s0 = g_esrc[i];
        float n0 = g_enorm[i];
        uint4 u0 = *(const uint4*)(g_B1h + (size_t)s0 * C + c8);
        const __half2* h0 = (const __half2*)&u0;
#pragma unroll
        for (int k = 0; k < 4; k++) {
            float2 f0 = __half22float2(h0[k]);
            a[2 * k + 0] += f0.x * n0;
            a[2 * k + 1] += f0.y * n0;
        }
    }

    // merge odd half into even half
#pragma unroll
    for (int k = 0; k < 8; k++) a[k] += __shfl_xor_sync(FULL, a[k], 16);

    if (half == 0) {
        float* p = g_B2 + (size_t)node * C + c8;     // holds self-loop term
        float4 u0 = *(const float4*)p;
        float4 u1 = *(const float4*)(p + 4);
        u0.x += a[0]; u0.y += a[1]; u0.z += a[2]; u0.w += a[3];
        u1.x += a[4]; u1.y += a[5]; u1.z += a[6]; u1.w += a[7];

        if (!POOL) {
            *(float4*)p       = u0;
            *(float4*)(p + 4) = u1;
        } else {
            unsigned g = (unsigned)batch[node];
            if (g >= NG) return;
            const float* bb = b2 + c8;
            float* q = g_sums + g * C + c8;
            atomicAdd(q + 0, lrelu(u0.x + bb[0]));
            atomicAdd(q + 1, lrelu(u0.y + bb[1]));
            atomicAdd(q + 2, lrelu(u0.z + bb[2]));
            atomicAdd(q + 3, lrelu(u0.w + bb[3]));
            atomicAdd(q + 4, lrelu(u1.x + bb[4]));
            atomicAdd(q + 5, lrelu(u1.y + bb[5]));
            atomicAdd(q + 6, lrelu(u1.z + bb[6]));
            atomicAdd(q + 7, lrelu(u1.w + bb[7]));
        }
    }
}

// ---------------- MLP head ---------------------------------------------------
__global__ __launch_bounds__(128)
void head_kernel(const float* __restrict__ W3, const float* __restrict__ b3,
                 const float* __restrict__ W4, const float* __restrict__ b4,
                 const float* __restrict__ W5, const float* __restrict__ b5,
                 float* __restrict__ out)
{
    int g = blockIdx.x;
    int t = threadIdx.x;
    __shared__ float gv[128], t1[64], t2[64];

    float inv = 1.0f / fmaxf(g_cnts[g], 1.0f);
    gv[t] = g_sums[g * C + t] * inv;
    __syncthreads();

    if (t < 64) {
        float s = b3[t];
#pragma unroll 8
        for (int k = 0; k < 128; k++) s += gv[k] * W3[k * 64 + t];
        t1[t] = lrelu(s);
    }
    __syncthreads();
    if (t < 64) {
        float s = b4[t];
#pragma unroll 8
        for (int k = 0; k < 64; k++) s += t1[k] * W4[k * 64 + t];
        t2[t] = lrelu(s);
    }
    __syncthreads();
    if (t < 10) {
        float s = b5[t];
#pragma unroll 8
        for (int k = 0; k < 64; k++) s += t2[k] * W5[k * 10 + t];
        out[g * 10 + t] = s;
    }
}

// ---------------- launch ----------------------------------------------------
// Inputs resolved by ELEMENT COUNT (ordering-agnostic). edge_index/batch are
// int32 (JAX x64 disabled downcasts int64 -> int32).
extern "C" void kernel_launch(void* const* d_in, const int* in_sizes, int n_in,
                              void* d_out, int out_size)
{
    const float* x = nullptr;
    const int* ei = nullptr;
    const int* batch = nullptr;
    const float *W1 = nullptr, *b1 = nullptr, *W2 = nullptr, *b2 = nullptr;
    const float *W3 = nullptr, *b3 = nullptr, *W4 = nullptr, *b4 = nullptr;
    const float *W5 = nullptr, *b5 = nullptr;

    for (int i = 0; i < n_in; i++) {
        const void* p = d_in[i];
        switch (in_sizes[i]) {
            case 12800000: x = (const float*)p; break;
            case 3200000:  ei = (const int*)p; break;
            case 100000:   batch = (const int*)p; break;
            case 16384:    if (!W1) W1 = (const float*)p; else W2 = (const float*)p; break;
            case 8192:     W3 = (const float*)p; break;
            case 4096:     W4 = (const float*)p; break;
            case 640:      W5 = (const float*)p; break;
            case 128:      if (!b1) b1 = (const float*)p; else b2 = (const float*)p; break;
            case 64:       if (!b3) b3 = (const float*)p; else b4 = (const float*)p; break;
            case 10:       b5 = (const float*)p; break;
            default: break;
        }
    }
    float* out = (float*)d_out;
    (void)out_size;

    // CSR build (once, reused by both layers)
    zero_prep_kernel<<<(N_NODES + 255) / 256, 256>>>();
    deg_kernel<<<(N_EDGES + 255) / 256, 256>>>(ei, batch);
    scan_kernel<<<1, 1024>>>();
    fill_kernel<<<(N_EDGES + 255) / 256, 256>>>(ei);

    // layer 1
    gemm_kernel<false><<<N_NODES / 32, 256>>>(x, W1, nullptr);
    agg_kernel<false><<<(N_NODES * 32 + 255) / 256, 256>>>(batch, b2);

    // layer 2 (pool fused into agg)
    gemm_kernel<true><<<N_NODES / 32, 256>>>(nullptr, W2, b1);
    agg_kernel<true><<<(N_NODES * 32 + 255) / 256, 256>>>(batch, b2);

    // MLP head
    head_kernel<<<NG, 128>>>(W3, b3, W4, b4, W5, b5, out);
}

// round 12
// speedup vs baseline: 1.3770x; 1.1937x over previous
#include <cuda_runtime.h>
#include <cuda_fp16.h>

#define N_NODES 100000
#define N_EDGES 1600000
#define C 128
#define NG 128
#define LSLOPE 0.01f

// ---------------- scratch (device globals: no allocation allowed) ----------
__device__ __align__(16) __half g_B1h[(size_t)N_NODES * C];  // H fp16 (25.6 MB, gathered)
__device__ __align__(16) float  g_B2[(size_t)N_NODES * C];   // layer-1 AGG (fp32)
__device__ int   g_deg_i[N_NODES];
__device__ float g_dinv[N_NODES];
__device__ int   g_off[N_NODES + 1];       // CSR offsets (by dst)
__device__ int   g_cursor[N_NODES];        // fill cursors
__device__ int   g_esrc[N_EDGES];          // src per CSR slot
__device__ float g_enorm[N_EDGES];         // dinv[s]*dinv[d] per CSR slot
__device__ __align__(16) float g_sums[NG * C];
__device__ float g_cnts[NG];

__device__ __forceinline__ float lrelu(float v) { return v > 0.f ? v : LSLOPE * v; }

// ---------------- degree histogram + graph counts ----------------------------
__global__ void deg_kernel(const int* __restrict__ ei, const int* __restrict__ batch) {
    int e = blockIdx.x * blockDim.x + threadIdx.x;
    if (e < N_EDGES) {
        unsigned d = (unsigned)ei[N_EDGES + e];
        if (d < N_NODES) atomicAdd(&g_deg_i[d], 1);
    }
    if (e < N_NODES) {
        unsigned g = (unsigned)batch[e];
        if (g < NG) atomicAdd(&g_cnts[g], 1.0f);
    }
}

// ---------------- single-block scan: offsets, cursors, dinv -----------------
__global__ __launch_bounds__(1024)
void scan_kernel() {
    __shared__ int part[1024];
    const int CHUNK = (N_NODES + 1023) / 1024;   // 98
    int t = threadIdx.x;
    int start = t * CHUNK;
    int end = min(start + CHUNK, N_NODES);

    int s = 0;
    for (int i = start; i < end; i++) s += g_deg_i[i];
    part[t] = s;
    __syncthreads();

    for (int off = 1; off < 1024; off <<= 1) {
        int v = (t >= off) ? part[t - off] : 0;
        __syncthreads();
        part[t] += v;
        __syncthreads();
    }

    int running = part[t] - s;   // exclusive base for this chunk
    for (int i = start; i < end; i++) {
        g_off[i] = running;
        g_cursor[i] = running;
        int d = g_deg_i[i];
        running += d;
        g_dinv[i] = rsqrtf((float)d + 1.0f);
    }
    if (t == 1023) g_off[N_NODES] = running;
}

// ---------------- CSR fill: permute edges by dst -----------------------------
__global__ void fill_kernel(const int* __restrict__ ei) {
    int e = blockIdx.x * blockDim.x + threadIdx.x;
    if (e >= N_EDGES) return;
    unsigned s = (unsigned)ei[e];
    unsigned d = (unsigned)ei[N_EDGES + e];
    if (s >= N_NODES || d >= N_NODES) return;
    int pos = atomicAdd(&g_cursor[d], 1);
    g_esrc[pos]  = (int)s;
    g_enorm[pos] = g_dinv[s] * g_dinv[d];
}

// ---------------- fused GEMM (R5 shape): H = act(X)@W -> B1h (fp16 only) ----
template <bool TRANSFORM>
__global__ __launch_bounds__(256)
void gemm_kernel(const float* __restrict__ Xext, const float* __restrict__ W,
                 const float* __restrict__ bin)
{
    __shared__ float  Xs[32][33];
    __shared__ float4 Ws4[32][32];   // [kk][col/4]

    const float* __restrict__ X = TRANSFORM ? (const float*)g_B2 : Xext;

    int tid  = threadIdx.x;
    int row0 = blockIdx.x * 32;
    int tx   = tid & 31;
    int ty   = tid >> 5;

    float acc[4][4];
#pragma unroll
    for (int i = 0; i < 4; i++)
#pragma unroll
        for (int j = 0; j < 4; j++) acc[i][j] = 0.f;

    for (int kt = 0; kt < 4; ++kt) {
        {
            int r = tid >> 3;
            int c = (tid & 7) * 4;
            int kcol = kt * 32 + c;
            float4 v = *(const float4*)(X + (size_t)(row0 + r) * C + kcol);
            if (TRANSFORM) {
                v.x = lrelu(v.x + bin[kcol + 0]);
                v.y = lrelu(v.y + bin[kcol + 1]);
                v.z = lrelu(v.z + bin[kcol + 2]);
                v.w = lrelu(v.w + bin[kcol + 3]);
            }
            Xs[r][c + 0] = v.x; Xs[r][c + 1] = v.y;
            Xs[r][c + 2] = v.z; Xs[r][c + 3] = v.w;
        }
#pragma unroll
        for (int i = 0; i < 4; i++) {
            int idx = tid + i * 256;
            int kk  = idx >> 5;
            int c4  = idx & 31;
            Ws4[kk][c4] = *(const float4*)(W + (size_t)(kt * 32 + kk) * C + c4 * 4);
        }
        __syncthreads();

#pragma unroll
        for (int kk = 0; kk < 32; ++kk) {
            float x0 = Xs[ty * 4 + 0][kk];
            float x1 = Xs[ty * 4 + 1][kk];
            float x2 = Xs[ty * 4 + 2][kk];
            float x3 = Xs[ty * 4 + 3][kk];
            float4 w = Ws4[kk][tx];
            acc[0][0] += x0 * w.x; acc[0][1] += x0 * w.y; acc[0][2] += x0 * w.z; acc[0][3] += x0 * w.w;
            acc[1][0] += x1 * w.x; acc[1][1] += x1 * w.y; acc[1][2] += x1 * w.z; acc[1][3] += x1 * w.w;
            acc[2][0] += x2 * w.x; acc[2][1] += x2 * w.y; acc[2][2] += x2 * w.z; acc[2][3] += x2 * w.w;
            acc[3][0] += x3 * w.x; acc[3][1] += x3 * w.y; acc[3][2] += x3 * w.z; acc[3][3] += x3 * w.w;
        }
        __syncthreads();
    }

    // epilogue: fp16 H only (self-loop handled inside agg)
#pragma unroll
    for (int i = 0; i < 4; i++) {
        int r = row0 + ty * 4 + i;
        __half2 h01 = __floats2half2_rn(acc[i][0], acc[i][1]);
        __half2 h23 = __floats2half2_rn(acc[i][2], acc[i][3]);
        uint2 packed;
        packed.x = *(unsigned*)&h01;
        packed.y = *(unsigned*)&h23;
        *(uint2*)(g_B1h + (size_t)r * C + tx * 4) = packed;
    }
}

// ---------------- aggregation (R5 structure, fp16 rows, self-loop fused) -----
// Warp per dst node; lane owns 4 channels (one uint2 = 4 halves per gather).
// AGG = B1[node]*dinv^2 + sum_e norm_e * B1[src_e]
// POOL=false: B2[node] = AGG                              (layer 1)
// POOL=true : sums[batch[node]] += lrelu(AGG + b2)        (layer 2 + pool)
template <bool POOL>
__global__ __launch_bounds__(256)
void agg_kernel(const int* __restrict__ batch, const float* __restrict__ b2)
{
    int node = (blockIdx.x * blockDim.x + threadIdx.x) >> 5;
    int lane = threadIdx.x & 31;
    if (node >= N_NODES) return;

    int beg = g_off[node];
    int end = g_off[node + 1];

    // self-loop term from own (L2-hot) row
    float d  = g_dinv[node];
    float d2 = d * d;
    uint2 su = *(const uint2*)(g_B1h + (size_t)node * C + lane * 4);
    float2 sf01 = __half22float2(*(__half2*)&su.x);
    float2 sf23 = __half22float2(*(__half2*)&su.y);

    float a0x = sf01.x * d2, a0y = sf01.y * d2, a0z = sf23.x * d2, a0w = sf23.y * d2;
    float a1x = 0.f, a1y = 0.f, a1z = 0.f, a1w = 0.f;

    int i = beg;
    for (; i + 2 <= end; i += 2) {
        int   s0 = g_esrc[i];
        int   s1 = g_esrc[i + 1];
        float n0 = g_enorm[i];
        float n1 = g_enorm[i + 1];
        uint2 u0 = *(const uint2*)(g_B1h + (size_t)s0 * C + lane * 4);
        uint2 u1 = *(const uint2*)(g_B1h + (size_t)s1 * C + lane * 4);
        float2 f0a = __half22float2(*(__half2*)&u0.x);
        float2 f0b = __half22float2(*(__half2*)&u0.y);
        float2 f1a = __half22float2(*(__half2*)&u1.x);
        float2 f1b = __half22float2(*(__half2*)&u1.y);
        a0x += f0a.x * n0; a0y += f0a.y * n0; a0z += f0b.x * n0; a0w += f0b.y * n0;
        a1x += f1a.x * n1; a1y += f1a.y * n1; a1z += f1b.x * n1; a1w += f1b.y * n1;
    }
    if (i < end) {
        int   s0 = g_esrc[i];
        float n0 = g_enorm[i];
        uint2 u0 = *(const uint2*)(g_B1h + (size_t)s0 * C + lane * 4);
        float2 f0a = __half22float2(*(__half2*)&u0.x);
        float2 f0b = __half22float2(*(__half2*)&u0.y);
        a0x += f0a.x * n0; a0y += f0a.y * n0; a0z += f0b.x * n0; a0w += f0b.y * n0;
    }

    float4 r = make_float4(a0x + a1x, a0y + a1y, a0z + a1z, a0w + a1w);

    if (!POOL) {
        *(float4*)(g_B2 + (size_t)node * C + lane * 4) = r;
    } else {
        unsigned g = (unsigned)batch[node];
        if (g >= NG) return;
        float4 b = *(const float4*)(b2 + lane * 4);
        float* q = g_sums + g * C + lane * 4;
        atomicAdd(q + 0, lrelu(r.x + b.x));
        atomicAdd(q + 1, lrelu(r.y + b.y));
        atomicAdd(q + 2, lrelu(r.z + b.z));
        atomicAdd(q + 3, lrelu(r.w + b.w));
    }
}

// ---------------- MLP head ---------------------------------------------------
__global__ __launch_bounds__(128)
void head_kernel(const float* __restrict__ W3, const float* __restrict__ b3,
                 const float* __restrict__ W4, const float* __restrict__ b4,
                 const float* __restrict__ W5, const float* __restrict__ b5,
                 float* __restrict__ out)
{
    int g = blockIdx.x;
    int t = threadIdx.x;
    __shared__ float gv[128], t1[64], t2[64];

    float inv = 1.0f / fmaxf(g_cnts[g], 1.0f);
    gv[t] = g_sums[g * C + t] * inv;
    __syncthreads();

    if (t < 64) {
        float s = b3[t];
#pragma unroll 8
        for (int k = 0; k < 128; k++) s += gv[k] * W3[k * 64 + t];
        t1[t] = lrelu(s);
    }
    __syncthreads();
    if (t < 64) {
        float s = b4[t];
#pragma unroll 8
        for (int k = 0; k < 64; k++) s += t1[k] * W4[k * 64 + t];
        t2[t] = lrelu(s);
    }
    __syncthreads();
    if (t < 10) {
        float s = b5[t];
#pragma unroll 8
        for (int k = 0; k < 64; k++) s += t2[k] * W5[k * 10 + t];
        out[g * 10 + t] = s;
    }
}

// ---------------- launch ----------------------------------------------------
// Inputs resolved by ELEMENT COUNT (ordering-agnostic). edge_index/batch are
// int32 (JAX x64 disabled downcasts int64 -> int32).
extern "C" void kernel_launch(void* const* d_in, const int* in_sizes, int n_in,
                              void* d_out, int out_size)
{
    const float* x = nullptr;
    const int* ei = nullptr;
    const int* batch = nullptr;
    const float *W1 = nullptr, *b1 = nullptr, *W2 = nullptr, *b2 = nullptr;
    const float *W3 = nullptr, *b3 = nullptr, *W4 = nullptr, *b4 = nullptr;
    const float *W5 = nullptr, *b5 = nullptr;

    for (int i = 0; i < n_in; i++) {
        const void* p = d_in[i];
        switch (in_sizes[i]) {
            case 12800000: x = (const float*)p; break;
            case 3200000:  ei = (const int*)p; break;
            case 100000:   batch = (const int*)p; break;
            case 16384:    if (!W1) W1 = (const float*)p; else W2 = (const float*)p; break;
            case 8192:     W3 = (const float*)p; break;
            case 4096:     W4 = (const float*)p; break;
            case 640:      W5 = (const float*)p; break;
            case 128:      if (!b1) b1 = (const float*)p; else b2 = (const float*)p; break;
            case 64:       if (!b3) b3 = (const float*)p; else b4 = (const float*)p; break;
            case 10:       b5 = (const float*)p; break;
            default: break;
        }
    }
    float* out = (float*)d_out;
    (void)out_size;

    // zero accumulators via async memsets (graph-capturable, no kernel slots)
    void *p_deg = nullptr, *p_sums = nullptr, *p_cnts = nullptr;
    cudaGetSymbolAddress(&p_deg,  g_deg_i);
    cudaGetSymbolAddress(&p_sums, g_sums);
    cudaGetSymbolAddress(&p_cnts, g_cnts);
    cudaMemsetAsync(p_deg,  0, N_NODES * sizeof(int));
    cudaMemsetAsync(p_sums, 0, NG * C * sizeof(float));
    cudaMemsetAsync(p_cnts, 0, NG * sizeof(float));

    // CSR build (once, reused by both layers)
    deg_kernel<<<(N_EDGES + 255) / 256, 256>>>(ei, batch);
    scan_kernel<<<1, 1024>>>();
    fill_kernel<<<(N_EDGES + 255) / 256, 256>>>(ei);

    // layer 1
    gemm_kernel<false><<<N_NODES / 32, 256>>>(x, W1, nullptr);
    agg_kernel<false><<<(N_NODES * 32 + 255) / 256, 256>>>(batch, b2);

    // layer 2 (pool fused into agg)
    gemm_kernel<true><<<N_NODES / 32, 256>>>(nullptr, W2, b1);
    agg_kernel<true><<<(N_NODES * 32 + 255) / 256, 256>>>(batch, b2);

    // MLP head
    head_kernel<<<NG, 128>>>(W3, b3, W4, b4, W5, b5, out);
}

// round 13
// speedup vs baseline: 1.4484x; 1.0518x over previous
#include <cuda_runtime.h>
#include <cuda_fp16.h>
#include <mma.h>

using namespace nvcuda;

#define N_NODES 100000
#define N_EDGES 1600000
#define C 128
#define NG 128
#define LSLOPE 0.01f

#define LDA 144            // smem leading dim (halves): 288B rows, 32B-aligned tiles
#define GEMM_SMEM ((64 + 128) * LDA * 2)   // 55296 bytes

// ---------------- scratch (device globals: no allocation allowed) ----------
__device__ __align__(16) float g_B1[(size_t)N_NODES * C];   // H fp32 (gathered)
__device__ __align__(16) float g_B2[(size_t)N_NODES * C];   // AGG / layer input
__device__ int   g_deg_i[N_NODES];
__device__ float g_dinv[N_NODES];
__device__ int   g_off[N_NODES + 1];       // CSR offsets (by dst)
__device__ int   g_cursor[N_NODES];        // fill cursors
__device__ int   g_esrc[N_EDGES];          // src per CSR slot
__device__ float g_enorm[N_EDGES];         // dinv[s]*dinv[d] per CSR slot
__device__ __align__(16) float g_sums[NG * C];
__device__ float g_cnts[NG];

__device__ __forceinline__ float lrelu(float v) { return v > 0.f ? v : LSLOPE * v; }

// ---------------- degree histogram + graph counts ----------------------------
__global__ void deg_kernel(const int* __restrict__ ei, const int* __restrict__ batch) {
    int e = blockIdx.x * blockDim.x + threadIdx.x;
    if (e < N_EDGES) {
        unsigned d = (unsigned)ei[N_EDGES + e];
        if (d < N_NODES) atomicAdd(&g_deg_i[d], 1);
    }
    if (e < N_NODES) {
        unsigned g = (unsigned)batch[e];
        if (g < NG) atomicAdd(&g_cnts[g], 1.0f);
    }
}

// ---------------- single-block scan: offsets, cursors, dinv -----------------
__global__ __launch_bounds__(1024)
void scan_kernel() {
    __shared__ int part[1024];
    const int CHUNK = (N_NODES + 1023) / 1024;   // 98
    int t = threadIdx.x;
    int start = t * CHUNK;
    int end = min(start + CHUNK, N_NODES);

    int s = 0;
    for (int i = start; i < end; i++) s += g_deg_i[i];
    part[t] = s;
    __syncthreads();

    for (int off = 1; off < 1024; off <<= 1) {
        int v = (t >= off) ? part[t - off] : 0;
        __syncthreads();
        part[t] += v;
        __syncthreads();
    }

    int running = part[t] - s;   // exclusive base for this chunk
    for (int i = start; i < end; i++) {
        g_off[i] = running;
        g_cursor[i] = running;
        int d = g_deg_i[i];
        running += d;
        g_dinv[i] = rsqrtf((float)d + 1.0f);
    }
    if (t == 1023) g_off[N_NODES] = running;
}

// ---------------- CSR fill: permute edges by dst -----------------------------
__global__ void fill_kernel(const int* __restrict__ ei) {
    int e = blockIdx.x * blockDim.x + threadIdx.x;
    if (e >= N_EDGES) return;
    unsigned s = (unsigned)ei[e];
    unsigned d = (unsigned)ei[N_EDGES + e];
    if (s >= N_NODES || d >= N_NODES) return;
    int pos = atomicAdd(&g_cursor[d], 1);
    g_esrc[pos]  = (int)s;
    g_enorm[pos] = g_dinv[s] * g_dinv[d];
}

// ---------------- WMMA fp16 GEMM: H = act(X)@W -> B1 ; AGG self = H*d2 -> B2 -
// CTA: 64x128 output tile, 256 threads (8 warps in 2x4), K=128 staged once.
template <bool TRANSFORM>
__global__ __launch_bounds__(256)
void gemm_kernel(const float* __restrict__ Xext, const float* __restrict__ W,
                 const float* __restrict__ bin)
{
    extern __shared__ char smem[];
    half* Xs = (half*)smem;                    // [64][LDA]
    half* Ws = (half*)(smem + 64 * LDA * 2);   // [128][LDA]

    const float* __restrict__ X = TRANSFORM ? (const float*)g_B2 : Xext;

    int tid  = threadIdx.x;
    int row0 = blockIdx.x * 64;

    // stage X tile 64x128 as fp16 (with optional transform)
#pragma unroll
    for (int it = 0; it < 8; it++) {
        int idx = tid + it * 256;          // float4 index: 0..2047
        int r   = idx >> 5;                // 32 float4 per row
        int c4  = (idx & 31) * 4;
        int grow = min(row0 + r, N_NODES - 1);
        float4 v = *(const float4*)(X + (size_t)grow * C + c4);
        if (TRANSFORM) {
            v.x = lrelu(v.x + bin[c4 + 0]);
            v.y = lrelu(v.y + bin[c4 + 1]);
            v.z = lrelu(v.z + bin[c4 + 2]);
            v.w = lrelu(v.w + bin[c4 + 3]);
        }
        half2* p = (half2*)(Xs + r * LDA + c4);
        p[0] = __floats2half2_rn(v.x, v.y);
        p[1] = __floats2half2_rn(v.z, v.w);
    }
    // stage W 128x128 as fp16
#pragma unroll
    for (int it = 0; it < 16; it++) {
        int idx = tid + it * 256;          // 0..4095
        int r   = idx >> 5;
        int c4  = (idx & 31) * 4;
        float4 v = *(const float4*)(W + (size_t)r * C + c4);
        half2* p = (half2*)(Ws + r * LDA + c4);
        p[0] = __floats2half2_rn(v.x, v.y);
        p[1] = __floats2half2_rn(v.z, v.w);
    }
    __syncthreads();

    int wid   = tid >> 5;
    int warpM = wid & 1;    // 0..1 (32-row strips)
    int warpN = wid >> 1;   // 0..3 (32-col strips)

    wmma::fragment<wmma::accumulator, 16, 16, 16, float> c[2][2];
#pragma unroll
    for (int i = 0; i < 2; i++)
#pragma unroll
        for (int j = 0; j < 2; j++) wmma::fill_fragment(c[i][j], 0.0f);

#pragma unroll
    for (int k = 0; k < C; k += 16) {
        wmma::fragment<wmma::matrix_a, 16, 16, 16, half, wmma::row_major> a[2];
        wmma::fragment<wmma::matrix_b, 16, 16, 16, half, wmma::row_major> b[2];
        wmma::load_matrix_sync(a[0], Xs + (warpM * 32 + 0)  * LDA + k, LDA);
        wmma::load_matrix_sync(a[1], Xs + (warpM * 32 + 16) * LDA + k, LDA);
        wmma::load_matrix_sync(b[0], Ws + k * LDA + warpN * 32 + 0,  LDA);
        wmma::load_matrix_sync(b[1], Ws + k * LDA + warpN * 32 + 16, LDA);
#pragma unroll
        for (int i = 0; i < 2; i++)
#pragma unroll
            for (int j = 0; j < 2; j++)
                wmma::mma_sync(c[i][j], a[i], b[j], c[i][j]);
    }

    // stage result to smem (reuse Xs/Ws region), then write B1 + self-loop B2
    __syncthreads();
    float* Cs = (float*)smem;   // [64][128] = 32 KB < 55 KB
#pragma unroll
    for (int i = 0; i < 2; i++)
#pragma unroll
        for (int j = 0; j < 2; j++)
            wmma::store_matrix_sync(Cs + (warpM * 32 + i * 16) * C + warpN * 32 + j * 16,
                                    c[i][j], C, wmma::mem_row_major);
    __syncthreads();

#pragma unroll
    for (int it = 0; it < 8; it++) {
        int idx = tid + it * 256;
        int r   = idx >> 5;
        int c4  = (idx & 31) * 4;
        int grow = row0 + r;
        if (grow < N_NODES) {
            float4 h = *(const float4*)(Cs + r * C + c4);
            *(float4*)(g_B1 + (size_t)grow * C + c4) = h;
            float d  = g_dinv[grow];
            float d2 = d * d;
            float4 a = make_float4(h.x * d2, h.y * d2, h.z * d2, h.w * d2);
            *(float4*)(g_B2 + (size_t)grow * C + c4) = a;
        }
    }
}

// ---------------- aggregation (R5 exact shape) --------------------------------
// Warp per dst node, lane owns 4 channels (float4), unroll-2.
// POOL=false: B2[node] += sum(norm * B1[src])            (layer 1)
// POOL=true : sums[batch[node]] += lrelu(AGG + b2)       (layer 2, fused pool)
template <bool POOL>
__global__ __launch_bounds__(256)
void agg_kernel(const int* __restrict__ batch, const float* __restrict__ b2)
{
    int node = (blockIdx.x * blockDim.x + threadIdx.x) >> 5;
    int lane = threadIdx.x & 31;
    if (node >= N_NODES) return;

    int beg = g_off[node];
    int end = g_off[node + 1];

    float4 a0 = make_float4(0.f, 0.f, 0.f, 0.f);
    float4 a1 = make_float4(0.f, 0.f, 0.f, 0.f);

    int i = beg;
    for (; i + 2 <= end; i += 2) {
        int   s0 = g_esrc[i];
        int   s1 = g_esrc[i + 1];
        float n0 = g_enorm[i];
        float n1 = g_enorm[i + 1];
        float4 v0 = *(const float4*)(g_B1 + (size_t)s0 * C + lane * 4);
        float4 v1 = *(const float4*)(g_B1 + (size_t)s1 * C + lane * 4);
        a0.x += v0.x * n0; a0.y += v0.y * n0; a0.z += v0.z * n0; a0.w += v0.w * n0;
        a1.x += v1.x * n1; a1.y += v1.y * n1; a1.z += v1.z * n1; a1.w += v1.w * n1;
    }
    if (i < end) {
        int   s0 = g_esrc[i];
        float n0 = g_enorm[i];
        float4 v0 = *(const float4*)(g_B1 + (size_t)s0 * C + lane * 4);
        a0.x += v0.x * n0; a0.y += v0.y * n0; a0.z += v0.z * n0; a0.w += v0.w * n0;
    }

    float* p = g_B2 + (size_t)node * C + lane * 4;   // holds self-loop term
    float4 cur = *(const float4*)p;
    cur.x += a0.x + a1.x;
    cur.y += a0.y + a1.y;
    cur.z += a0.z + a1.z;
    cur.w += a0.w + a1.w;

    if (!POOL) {
        *(float4*)p = cur;
    } else {
        unsigned g = (unsigned)batch[node];
        if (g >= NG) return;
        float4 b = *(const float4*)(b2 + lane * 4);
        float* q = g_sums + g * C + lane * 4;
        atomicAdd(q + 0, lrelu(cur.x + b.x));
        atomicAdd(q + 1, lrelu(cur.y + b.y));
        atomicAdd(q + 2, lrelu(cur.z + b.z));
        atomicAdd(q + 3, lrelu(cur.w + b.w));
    }
}

// ---------------- MLP head ---------------------------------------------------
__global__ __launch_bounds__(128)
void head_kernel(const float* __restrict__ W3, const float* __restrict__ b3,
                 const float* __restrict__ W4, const float* __restrict__ b4,
                 const float* __restrict__ W5, const float* __restrict__ b5,
                 float* __restrict__ out)
{
    int g = blockIdx.x;
    int t = threadIdx.x;
    __shared__ float gv[128], t1[64], t2[64];

    float inv = 1.0f / fmaxf(g_cnts[g], 1.0f);
    gv[t] = g_sums[g * C + t] * inv;
    __syncthreads();

    if (t < 64) {
        float s = b3[t];
#pragma unroll 8
        for (int k = 0; k < 128; k++) s += gv[k] * W3[k * 64 + t];
        t1[t] = lrelu(s);
    }
    __syncthreads();
    if (t < 64) {
        float s = b4[t];
#pragma unroll 8
        for (int k = 0; k < 64; k++) s += t1[k] * W4[k * 64 + t];
        t2[t] = lrelu(s);
    }
    __syncthreads();
    if (t < 10) {
        float s = b5[t];
#pragma unroll 8
        for (int k = 0; k < 64; k++) s += t2[k] * W5[k * 10 + t];
        out[g * 10 + t] = s;
    }
}

// ---------------- launch ----------------------------------------------------
// Inputs resolved by ELEMENT COUNT (ordering-agnostic). edge_index/batch are
// int32 (JAX x64 disabled downcasts int64 -> int32).
extern "C" void kernel_launch(void* const* d_in, const int* in_sizes, int n_in,
                              void* d_out, int out_size)
{
    const float* x = nullptr;
    const int* ei = nullptr;
    const int* batch = nullptr;
    const float *W1 = nullptr, *b1 = nullptr, *W2 = nullptr, *b2 = nullptr;
    const float *W3 = nullptr, *b3 = nullptr, *W4 = nullptr, *b4 = nullptr;
    const float *W5 = nullptr, *b5 = nullptr;

    for (int i = 0; i < n_in; i++) {
        const void* p = d_in[i];
        switch (in_sizes[i]) {
            case 12800000: x = (const float*)p; break;
            case 3200000:  ei = (const int*)p; break;
            case 100000:   batch = (const int*)p; break;
            case 16384:    if (!W1) W1 = (const float*)p; else W2 = (const float*)p; break;
            case 8192:     W3 = (const float*)p; break;
            case 4096:     W4 = (const float*)p; break;
            case 640:      W5 = (const float*)p; break;
            case 128:      if (!b1) b1 = (const float*)p; else b2 = (const float*)p; break;
            case 64:       if (!b3) b3 = (const float*)p; else b4 = (const float*)p; break;
            case 10:       b5 = (const float*)p; break;
            default: break;
        }
    }
    float* out = (float*)d_out;
    (void)out_size;

    // allow >48KB dynamic smem for the WMMA GEMM (idempotent, no allocation)
    static bool attr_done = false;
    if (!attr_done) {
        cudaFuncSetAttribute(gemm_kernel<false>,
                             cudaFuncAttributeMaxDynamicSharedMemorySize, GEMM_SMEM);
        cudaFuncSetAttribute(gemm_kernel<true>,
                             cudaFuncAttributeMaxDynamicSharedMemorySize, GEMM_SMEM);
        attr_done = true;
    }

    // zero accumulators via async memsets (graph-capturable, no allocation)
    void *p_deg = nullptr, *p_sums = nullptr, *p_cnts = nullptr;
    cudaGetSymbolAddress(&p_deg,  g_deg_i);
    cudaGetSymbolAddress(&p_sums, g_sums);
    cudaGetSymbolAddress(&p_cnts, g_cnts);
    cudaMemsetAsync(p_deg,  0, N_NODES * sizeof(int));
    cudaMemsetAsync(p_sums, 0, NG * C * sizeof(float));
    cudaMemsetAsync(p_cnts, 0, NG * sizeof(float));

    // CSR build (once, reused by both layers)
    deg_kernel<<<(N_EDGES + 255) / 256, 256>>>(ei, batch);
    scan_kernel<<<1, 1024>>>();
    fill_kernel<<<(N_EDGES + 255) / 256, 256>>>(ei);

    const int GEMM_GRID = (N_NODES + 63) / 64;   // 1563

    // layer 1
    gemm_kernel<false><<<GEMM_GRID, 256, GEMM_SMEM>>>(x, W1, nullptr);
    agg_kernel<false><<<(N_NODES * 32 + 255) / 256, 256>>>(batch, b2);

    // layer 2 (pool fused into agg)
    gemm_kernel<true><<<GEMM_GRID, 256, GEMM_SMEM>>>(nullptr, W2, b1);
    agg_kernel<true><<<(N_NODES * 32 + 255) / 256, 256>>>(batch, b2);

    // MLP head
    head_kernel<<<NG, 128>>>(W3, b3, W4, b4, W5, b5, out);
}

// round 14
// speedup vs baseline: 1.9771x; 1.3650x over previous
#include <cuda_runtime.h>
#include <cuda_fp16.h>
#include <mma.h>

using namespace nvcuda;

#define N_NODES 100000
#define N_EDGES 1600000
#define C 128
#define NG 128
#define LSLOPE 0.01f
#define FULL 0xffffffffu
#define NBLK ((N_NODES + 255) / 256)        // 391

#define LDA 144            // smem leading dim (halves)
#define GEMM_SMEM ((64 + 128) * LDA * 2)   // 55296 bytes

// ---------------- scratch (device globals: no allocation allowed) ----------
__device__ __align__(16) float g_B1[(size_t)N_NODES * C];   // H fp32 (gathered)
__device__ __align__(16) float g_B2[(size_t)N_NODES * C];   // AGG / layer input
__device__ int   g_deg_i[N_NODES];
__device__ float g_dinv[N_NODES];
__device__ int   g_off[N_NODES + 1];       // CSR offsets (by dst)
__device__ int   g_cursor[N_NODES];        // fill cursors
__device__ int2  g_edge[N_EDGES];          // {src, norm-as-int} per CSR slot
__device__ int   g_psum[NBLK];             // per-block degree sums
__device__ int   g_pbase[NBLK];            // exclusive block bases
__device__ __align__(16) float g_sums[NG * C];
__device__ float g_cnts[NG];

__device__ __forceinline__ float lrelu(float v) { return v > 0.f ? v : LSLOPE * v; }

// ---------------- degree histogram + graph counts ----------------------------
__global__ void deg_kernel(const int* __restrict__ ei, const int* __restrict__ batch) {
    int e = blockIdx.x * blockDim.x + threadIdx.x;
    if (e < N_EDGES) {
        unsigned d = (unsigned)ei[N_EDGES + e];
        if (d < N_NODES) atomicAdd(&g_deg_i[d], 1);
    }
    if (e < N_NODES) {
        unsigned g = (unsigned)batch[e];
        if (g < NG) atomicAdd(&g_cnts[g], 1.0f);
    }
}

// ---------------- CSR build: coalesced 3-step scan ---------------------------
__global__ __launch_bounds__(256)
void block_sum_kernel() {
    int t = threadIdx.x;
    int i = blockIdx.x * 256 + t;
    int d = (i < N_NODES) ? g_deg_i[i] : 0;
#pragma unroll
    for (int off = 16; off; off >>= 1) d += __shfl_down_sync(FULL, d, off);
    __shared__ int ws[8];
    if ((t & 31) == 0) ws[t >> 5] = d;
    __syncthreads();
    if (t == 0) {
        int s = 0;
#pragma unroll
        for (int k = 0; k < 8; k++) s += ws[k];
        g_psum[blockIdx.x] = s;
    }
}

__global__ __launch_bounds__(512)
void scan_partials_kernel() {
    __shared__ int sh[512];
    int t = threadIdx.x;
    int v = (t < NBLK) ? g_psum[t] : 0;
    sh[t] = v;
    __syncthreads();
    for (int off = 1; off < 512; off <<= 1) {
        int u = (t >= off) ? sh[t - off] : 0;
        __syncthreads();
        sh[t] += u;
        __syncthreads();
    }
    if (t < NBLK) g_pbase[t] = sh[t] - v;
    if (t == NBLK - 1) g_off[N_NODES] = sh[t];
}

__global__ __launch_bounds__(256)
void csr_emit_kernel() {
    int t = threadIdx.x;
    int lane = t & 31, w = t >> 5;
    int i = blockIdx.x * 256 + t;
    int d = (i < N_NODES) ? g_deg_i[i] : 0;

    // inclusive scan within warp
    int v = d;
#pragma unroll
    for (int off = 1; off < 32; off <<= 1) {
        int u = __shfl_up_sync(FULL, v, off);
        if (lane >= off) v += u;
    }
    __shared__ int wsum[8];
    if (lane == 31) wsum[w] = v;
    __syncthreads();
    if (t < 8) {
        int s = wsum[t];
#pragma unroll
        for (int off = 1; off < 8; off <<= 1) {
            int u = __shfl_up_sync(0xffu, s, off);
            if (t >= off) s += u;
        }
        wsum[t] = s;
    }
    __syncthreads();

    if (i < N_NODES) {
        int base = g_pbase[blockIdx.x] + (w > 0 ? wsum[w - 1] : 0);
        int excl = base + v - d;
        g_off[i]    = excl;
        g_cursor[i] = excl;
        g_dinv[i]   = rsqrtf((float)d + 1.0f);
    }
}

// ---------------- CSR fill: permute edges by dst, packed {src, norm} ---------
__global__ void fill_kernel(const int* __restrict__ ei) {
    int e = blockIdx.x * blockDim.x + threadIdx.x;
    if (e >= N_EDGES) return;
    unsigned s = (unsigned)ei[e];
    unsigned d = (unsigned)ei[N_EDGES + e];
    if (s >= N_NODES || d >= N_NODES) return;
    int pos = atomicAdd(&g_cursor[d], 1);
    float norm = g_dinv[s] * g_dinv[d];
    g_edge[pos] = make_int2((int)s, __float_as_int(norm));
}

// ---------------- WMMA fp16 GEMM: H = act(X)@W -> B1 ; self-loop -> B2 -------
template <bool TRANSFORM>
__global__ __launch_bounds__(256)
void gemm_kernel(const float* __restrict__ Xext, const float* __restrict__ W,
                 const float* __restrict__ bin)
{
    extern __shared__ char smem[];
    half* Xs = (half*)smem;                    // [64][LDA]
    half* Ws = (half*)(smem + 64 * LDA * 2);   // [128][LDA]

    const float* __restrict__ X = TRANSFORM ? (const float*)g_B2 : Xext;

    int tid  = threadIdx.x;
    int row0 = blockIdx.x * 64;

#pragma unroll
    for (int it = 0; it < 8; it++) {
        int idx = tid + it * 256;
        int r   = idx >> 5;
        int c4  = (idx & 31) * 4;
        int grow = min(row0 + r, N_NODES - 1);
        float4 v = *(const float4*)(X + (size_t)grow * C + c4);
        if (TRANSFORM) {
            v.x = lrelu(v.x + bin[c4 + 0]);
            v.y = lrelu(v.y + bin[c4 + 1]);
            v.z = lrelu(v.z + bin[c4 + 2]);
            v.w = lrelu(v.w + bin[c4 + 3]);
        }
        half2* p = (half2*)(Xs + r * LDA + c4);
        p[0] = __floats2half2_rn(v.x, v.y);
        p[1] = __floats2half2_rn(v.z, v.w);
    }
#pragma unroll
    for (int it = 0; it < 16; it++) {
        int idx = tid + it * 256;
        int r   = idx >> 5;
        int c4  = (idx & 31) * 4;
        float4 v = *(const float4*)(W + (size_t)r * C + c4);
        half2* p = (half2*)(Ws + r * LDA + c4);
        p[0] = __floats2half2_rn(v.x, v.y);
        p[1] = __floats2half2_rn(v.z, v.w);
    }
    __syncthreads();

    int wid   = tid >> 5;
    int warpM = wid & 1;
    int warpN = wid >> 1;

    wmma::fragment<wmma::accumulator, 16, 16, 16, float> c[2][2];
#pragma unroll
    for (int i = 0; i < 2; i++)
#pragma unroll
        for (int j = 0; j < 2; j++) wmma::fill_fragment(c[i][j], 0.0f);

#pragma unroll
    for (int k = 0; k < C; k += 16) {
        wmma::fragment<wmma::matrix_a, 16, 16, 16, half, wmma::row_major> a[2];
        wmma::fragment<wmma::matrix_b, 16, 16, 16, half, wmma::row_major> b[2];
        wmma::load_matrix_sync(a[0], Xs + (warpM * 32 + 0)  * LDA + k, LDA);
        wmma::load_matrix_sync(a[1], Xs + (warpM * 32 + 16) * LDA + k, LDA);
        wmma::load_matrix_sync(b[0], Ws + k * LDA + warpN * 32 + 0,  LDA);
        wmma::load_matrix_sync(b[1], Ws + k * LDA + warpN * 32 + 16, LDA);
#pragma unroll
        for (int i = 0; i < 2; i++)
#pragma unroll
            for (int j = 0; j < 2; j++)
                wmma::mma_sync(c[i][j], a[i], b[j], c[i][j]);
    }

    __syncthreads();
    float* Cs = (float*)smem;   // [64][128]
#pragma unroll
    for (int i = 0; i < 2; i++)
#pragma unroll
        for (int j = 0; j < 2; j++)
            wmma::store_matrix_sync(Cs + (warpM * 32 + i * 16) * C + warpN * 32 + j * 16,
                                    c[i][j], C, wmma::mem_row_major);
    __syncthreads();

#pragma unroll
    for (int it = 0; it < 8; it++) {
        int idx = tid + it * 256;
        int r   = idx >> 5;
        int c4  = (idx & 31) * 4;
        int grow = row0 + r;
        if (grow < N_NODES) {
            float4 h = *(const float4*)(Cs + r * C + c4);
            *(float4*)(g_B1 + (size_t)grow * C + c4) = h;
            float d  = g_dinv[grow];
            float d2 = d * d;
            float4 a = make_float4(h.x * d2, h.y * d2, h.z * d2, h.w * d2);
            *(float4*)(g_B2 + (size_t)grow * C + c4) = a;
        }
    }
}

// ---------------- aggregation (R5 shape, packed edges) ------------------------
// POOL=false: B2[node] += sum(norm * B1[src])            (layer 1)
// POOL=true : sums[batch[node]] += lrelu(AGG + b2)       (layer 2, fused pool)
template <bool POOL>
__global__ __launch_bounds__(256)
void agg_kernel(const int* __restrict__ batch, const float* __restrict__ b2)
{
    int node = (blockIdx.x * blockDim.x + threadIdx.x) >> 5;
    int lane = threadIdx.x & 31;
    if (node >= N_NODES) return;

    int beg = g_off[node];
    int end = g_off[node + 1];

    float4 a0 = make_float4(0.f, 0.f, 0.f, 0.f);
    float4 a1 = make_float4(0.f, 0.f, 0.f, 0.f);

    int i = beg;
    for (; i + 2 <= end; i += 2) {
        int2 e0 = g_edge[i];
        int2 e1 = g_edge[i + 1];
        float n0 = __int_as_float(e0.y);
        float n1 = __int_as_float(e1.y);
        float4 v0 = *(const float4*)(g_B1 + (size_t)e0.x * C + lane * 4);
        float4 v1 = *(const float4*)(g_B1 + (size_t)e1.x * C + lane * 4);
        a0.x += v0.x * n0; a0.y += v0.y * n0; a0.z += v0.z * n0; a0.w += v0.w * n0;
        a1.x += v1.x * n1; a1.y += v1.y * n1; a1.z += v1.z * n1; a1.w += v1.w * n1;
    }
    if (i < end) {
        int2 e0 = g_edge[i];
        float n0 = __int_as_float(e0.y);
        float4 v0 = *(const float4*)(g_B1 + (size_t)e0.x * C + lane * 4);
        a0.x += v0.x * n0; a0.y += v0.y * n0; a0.z += v0.z * n0; a0.w += v0.w * n0;
    }

    float* p = g_B2 + (size_t)node * C + lane * 4;   // holds self-loop term
    float4 cur = *(const float4*)p;
    cur.x += a0.x + a1.x;
    cur.y += a0.y + a1.y;
    cur.z += a0.z + a1.z;
    cur.w += a0.w + a1.w;

    if (!POOL) {
        *(float4*)p = cur;
    } else {
        unsigned g = (unsigned)batch[node];
        if (g >= NG) return;
        float4 b = *(const float4*)(b2 + lane * 4);
        float* q = g_sums + g * C + lane * 4;
        atomicAdd(q + 0, lrelu(cur.x + b.x));
        atomicAdd(q + 1, lrelu(cur.y + b.y));
        atomicAdd(q + 2, lrelu(cur.z + b.z));
        atomicAdd(q + 3, lrelu(cur.w + b.w));
    }
}

// ---------------- MLP head ---------------------------------------------------
__global__ __launch_bounds__(128)
void head_kernel(const float* __restrict__ W3, const float* __restrict__ b3,
                 const float* __restrict__ W4, const float* __restrict__ b4,
                 const float* __restrict__ W5, const float* __restrict__ b5,
                 float* __restrict__ out)
{
    int g = blockIdx.x;
    int t = threadIdx.x;
    __shared__ float gv[128], t1[64], t2[64];

    float inv = 1.0f / fmaxf(g_cnts[g], 1.0f);
    gv[t] = g_sums[g * C + t] * inv;
    __syncthreads();

    if (t < 64) {
        float s = b3[t];
#pragma unroll 8
        for (int k = 0; k < 128; k++) s += gv[k] * W3[k * 64 + t];
        t1[t] = lrelu(s);
    }
    __syncthreads();
    if (t < 64) {
        float s = b4[t];
#pragma unroll 8
        for (int k = 0; k < 64; k++) s += t1[k] * W4[k * 64 + t];
        t2[t] = lrelu(s);
    }
    __syncthreads();
    if (t < 10) {
        float s = b5[t];
#pragma unroll 8
        for (int k = 0; k < 64; k++) s += t2[k] * W5[k * 10 + t];
        out[g * 10 + t] = s;
    }
}

// ---------------- launch ----------------------------------------------------
// Inputs resolved by ELEMENT COUNT (ordering-agnostic). edge_index/batch are
// int32 (JAX x64 disabled downcasts int64 -> int32).
extern "C" void kernel_launch(void* const* d_in, const int* in_sizes, int n_in,
                              void* d_out, int out_size)
{
    const float* x = nullptr;
    const int* ei = nullptr;
    const int* batch = nullptr;
    const float *W1 = nullptr, *b1 = nullptr, *W2 = nullptr, *b2 = nullptr;
    const float *W3 = nullptr, *b3 = nullptr, *W4 = nullptr, *b4 = nullptr;
    const float *W5 = nullptr, *b5 = nullptr;

    for (int i = 0; i < n_in; i++) {
        const void* p = d_in[i];
        switch (in_sizes[i]) {
            case 12800000: x = (const float*)p; break;
            case 3200000:  ei = (const int*)p; break;
            case 100000:   batch = (const int*)p; break;
            case 16384:    if (!W1) W1 = (const float*)p; else W2 = (const float*)p; break;
            case 8192:     W3 = (const float*)p; break;
            case 4096:     W4 = (const float*)p; break;
            case 640:      W5 = (const float*)p; break;
            case 128:      if (!b1) b1 = (const float*)p; else b2 = (const float*)p; break;
            case 64:       if (!b3) b3 = (const float*)p; else b4 = (const float*)p; break;
            case 10:       b5 = (const float*)p; break;
            default: break;
        }
    }
    float* out = (float*)d_out;
    (void)out_size;

    static bool attr_done = false;
    if (!attr_done) {
        cudaFuncSetAttribute(gemm_kernel<false>,
                             cudaFuncAttributeMaxDynamicSharedMemorySize, GEMM_SMEM);
        cudaFuncSetAttribute(gemm_kernel<true>,
                             cudaFuncAttributeMaxDynamicSharedMemorySize, GEMM_SMEM);
        attr_done = true;
    }

    // zero accumulators via async memsets (graph-capturable, no allocation)
    void *p_deg = nullptr, *p_sums = nullptr, *p_cnts = nullptr;
    cudaGetSymbolAddress(&p_deg,  g_deg_i);
    cudaGetSymbolAddress(&p_sums, g_sums);
    cudaGetSymbolAddress(&p_cnts, g_cnts);
    cudaMemsetAsync(p_deg,  0, N_NODES * sizeof(int));
    cudaMemsetAsync(p_sums, 0, NG * C * sizeof(float));
    cudaMemsetAsync(p_cnts, 0, NG * sizeof(float));

    // CSR build: histogram -> coalesced 3-step scan -> fill
    deg_kernel<<<(N_EDGES + 255) / 256, 256>>>(ei, batch);
    block_sum_kernel<<<NBLK, 256>>>();
    scan_partials_kernel<<<1, 512>>>();
    csr_emit_kernel<<<NBLK, 256>>>();
    fill_kernel<<<(N_EDGES + 255) / 256, 256>>>(ei);

    const int GEMM_GRID = (N_NODES + 63) / 64;   // 1563

    // layer 1
    gemm_kernel<false><<<GEMM_GRID, 256, GEMM_SMEM>>>(x, W1, nullptr);
    agg_kernel<false><<<(N_NODES * 32 + 255) / 256, 256>>>(batch, b2);

    // layer 2 (pool fused into agg)
    gemm_kernel<true><<<GEMM_GRID, 256, GEMM_SMEM>>>(nullptr, W2, b1);
    agg_kernel<true><<<(N_NODES * 32 + 255) / 256, 256>>>(batch, b2);

    // MLP head
    head_kernel<<<NG, 128>>>(W3, b3, W4, b4, W5, b5, out);
}

// round 15
// speedup vs baseline: 2.1493x; 1.0871x over previous
#include <cuda_runtime.h>
#include <cuda_fp16.h>
#include <mma.h>

using namespace nvcuda;

#define N_NODES 100000
#define N_EDGES 1600000
#define C 128
#define NG 128
#define LSLOPE 0.01f
#define FULL 0xffffffffu
#define NBLK ((N_NODES + 255) / 256)        // 391

#define LDA 144            // smem leading dim (halves)
#define GEMM_SMEM ((64 + 128) * LDA * 2)   // 55296 bytes

// ---------------- scratch (device globals: no allocation allowed) ----------
__device__ __align__(16) __half g_B1h[(size_t)N_NODES * C];  // H fp16 (25.6 MB, gathered)
__device__ __align__(16) float  g_B2[(size_t)N_NODES * C];   // AGG / layer input
__device__ int   g_deg_i[N_NODES];
__device__ float g_dinv[N_NODES];
__device__ int   g_off[N_NODES + 1];       // CSR offsets (by dst)
__device__ int   g_cursor[N_NODES];        // fill cursors
__device__ int2  g_edge[N_EDGES];          // {src, norm-as-int} per CSR slot
__device__ int   g_psum[NBLK];             // per-block degree sums
__device__ int   g_pbase[NBLK];            // exclusive block bases
__device__ __align__(16) float g_sums[NG * C];
__device__ float g_cnts[NG];

__device__ __forceinline__ float lrelu(float v) { return v > 0.f ? v : LSLOPE * v; }

// ---------------- degree histogram + graph counts ----------------------------
__global__ void deg_kernel(const int* __restrict__ ei, const int* __restrict__ batch) {
    int e = blockIdx.x * blockDim.x + threadIdx.x;
    if (e < N_EDGES) {
        unsigned d = (unsigned)ei[N_EDGES + e];
        if (d < N_NODES) atomicAdd(&g_deg_i[d], 1);
    }
    if (e < N_NODES) {
        unsigned g = (unsigned)batch[e];
        if (g < NG) atomicAdd(&g_cnts[g], 1.0f);
    }
}

// ---------------- CSR build: coalesced 3-step scan ---------------------------
__global__ __launch_bounds__(256)
void block_sum_kernel() {
    int t = threadIdx.x;
    int i = blockIdx.x * 256 + t;
    int d = (i < N_NODES) ? g_deg_i[i] : 0;
#pragma unroll
    for (int off = 16; off; off >>= 1) d += __shfl_down_sync(FULL, d, off);
    __shared__ int ws[8];
    if ((t & 31) == 0) ws[t >> 5] = d;
    __syncthreads();
    if (t == 0) {
        int s = 0;
#pragma unroll
        for (int k = 0; k < 8; k++) s += ws[k];
        g_psum[blockIdx.x] = s;
    }
}

__global__ __launch_bounds__(512)
void scan_partials_kernel() {
    __shared__ int sh[512];
    int t = threadIdx.x;
    int v = (t < NBLK) ? g_psum[t] : 0;
    sh[t] = v;
    __syncthreads();
    for (int off = 1; off < 512; off <<= 1) {
        int u = (t >= off) ? sh[t - off] : 0;
        __syncthreads();
        sh[t] += u;
        __syncthreads();
    }
    if (t < NBLK) g_pbase[t] = sh[t] - v;
    if (t == NBLK - 1) g_off[N_NODES] = sh[t];
}

__global__ __launch_bounds__(256)
void csr_emit_kernel() {
    int t = threadIdx.x;
    int lane = t & 31, w = t >> 5;
    int i = blockIdx.x * 256 + t;
    int d = (i < N_NODES) ? g_deg_i[i] : 0;

    int v = d;
#pragma unroll
    for (int off = 1; off < 32; off <<= 1) {
        int u = __shfl_up_sync(FULL, v, off);
        if (lane >= off) v += u;
    }
    __shared__ int wsum[8];
    if (lane == 31) wsum[w] = v;
    __syncthreads();
    if (t < 8) {
        int s = wsum[t];
#pragma unroll
        for (int off = 1; off < 8; off <<= 1) {
            int u = __shfl_up_sync(0xffu, s, off);
            if (t >= off) s += u;
        }
        wsum[t] = s;
    }
    __syncthreads();

    if (i < N_NODES) {
        int base = g_pbase[blockIdx.x] + (w > 0 ? wsum[w - 1] : 0);
        int excl = base + v - d;
        g_off[i]    = excl;
        g_cursor[i] = excl;
        g_dinv[i]   = rsqrtf((float)d + 1.0f);
    }
}

// ---------------- CSR fill: permute edges by dst, packed {src, norm} ---------
__global__ void fill_kernel(const int* __restrict__ ei) {
    int e = blockIdx.x * blockDim.x + threadIdx.x;
    if (e >= N_EDGES) return;
    unsigned s = (unsigned)ei[e];
    unsigned d = (unsigned)ei[N_EDGES + e];
    if (s >= N_NODES || d >= N_NODES) return;
    int pos = atomicAdd(&g_cursor[d], 1);
    float norm = g_dinv[s] * g_dinv[d];
    g_edge[pos] = make_int2((int)s, __float_as_int(norm));
}

// ---------------- WMMA fp16 GEMM: H = act(X)@W -> B1h(fp16); self-loop -> B2 -
template <bool TRANSFORM>
__global__ __launch_bounds__(256)
void gemm_kernel(const float* __restrict__ Xext, const float* __restrict__ W,
                 const float* __restrict__ bin)
{
    extern __shared__ char smem[];
    half* Xs = (half*)smem;                    // [64][LDA]
    half* Ws = (half*)(smem + 64 * LDA * 2);   // [128][LDA]

    const float* __restrict__ X = TRANSFORM ? (const float*)g_B2 : Xext;

    int tid  = threadIdx.x;
    int row0 = blockIdx.x * 64;

#pragma unroll
    for (int it = 0; it < 8; it++) {
        int idx = tid + it * 256;
        int r   = idx >> 5;
        int c4  = (idx & 31) * 4;
        int grow = min(row0 + r, N_NODES - 1);
        float4 v = *(const float4*)(X + (size_t)grow * C + c4);
        if (TRANSFORM) {
            v.x = lrelu(v.x + bin[c4 + 0]);
            v.y = lrelu(v.y + bin[c4 + 1]);
            v.z = lrelu(v.z + bin[c4 + 2]);
            v.w = lrelu(v.w + bin[c4 + 3]);
        }
        half2* p = (half2*)(Xs + r * LDA + c4);
        p[0] = __floats2half2_rn(v.x, v.y);
        p[1] = __floats2half2_rn(v.z, v.w);
    }
#pragma unroll
    for (int it = 0; it < 16; it++) {
        int idx = tid + it * 256;
        int r   = idx >> 5;
        int c4  = (idx & 31) * 4;
        float4 v = *(const float4*)(W + (size_t)r * C + c4);
        half2* p = (half2*)(Ws + r * LDA + c4);
        p[0] = __floats2half2_rn(v.x, v.y);
        p[1] = __floats2half2_rn(v.z, v.w);
    }
    __syncthreads();

    int wid   = tid >> 5;
    int warpM = wid & 1;
    int warpN = wid >> 1;

    wmma::fragment<wmma::accumulator, 16, 16, 16, float> c[2][2];
#pragma unroll
    for (int i = 0; i < 2; i++)
#pragma unroll
        for (int j = 0; j < 2; j++) wmma::fill_fragment(c[i][j], 0.0f);

#pragma unroll
    for (int k = 0; k < C; k += 16) {
        wmma::fragment<wmma::matrix_a, 16, 16, 16, half, wmma::row_major> a[2];
        wmma::fragment<wmma::matrix_b, 16, 16, 16, half, wmma::row_major> b[2];
        wmma::load_matrix_sync(a[0], Xs + (warpM * 32 + 0)  * LDA + k, LDA);
        wmma::load_matrix_sync(a[1], Xs + (warpM * 32 + 16) * LDA + k, LDA);
        wmma::load_matrix_sync(b[0], Ws + k * LDA + warpN * 32 + 0,  LDA);
        wmma::load_matrix_sync(b[1], Ws + k * LDA + warpN * 32 + 16, LDA);
#pragma unroll
        for (int i = 0; i < 2; i++)
#pragma unroll
            for (int j = 0; j < 2; j++)
                wmma::mma_sync(c[i][j], a[i], b[j], c[i][j]);
    }

    __syncthreads();
    float* Cs = (float*)smem;   // [64][128]
#pragma unroll
    for (int i = 0; i < 2; i++)
#pragma unroll
        for (int j = 0; j < 2; j++)
            wmma::store_matrix_sync(Cs + (warpM * 32 + i * 16) * C + warpN * 32 + j * 16,
                                    c[i][j], C, wmma::mem_row_major);
    __syncthreads();

#pragma unroll
    for (int it = 0; it < 8; it++) {
        int idx = tid + it * 256;
        int r   = idx >> 5;
        int c4  = (idx & 31) * 4;
        int grow = row0 + r;
        if (grow < N_NODES) {
            float4 h = *(const float4*)(Cs + r * C + c4);
            // fp16 H (gathered by agg)
            __half2 h01 = __floats2half2_rn(h.x, h.y);
            __half2 h23 = __floats2half2_rn(h.z, h.w);
            uint2 packed;
            packed.x = *(unsigned*)&h01;
            packed.y = *(unsigned*)&h23;
            *(uint2*)(g_B1h + (size_t)grow * C + c4) = packed;
            // fp32 self-loop term
            float d  = g_dinv[grow];
            float d2 = d * d;
            float4 a = make_float4(h.x * d2, h.y * d2, h.z * d2, h.w * d2);
            *(float4*)(g_B2 + (size_t)grow * C + c4) = a;
        }
    }
}

// ---------------- aggregation (R14 shape, fp16 gathers) -----------------------
// Warp per dst node, lane owns 4 channels (uint2 = 4 halves), unroll-2.
// POOL=false: B2[node] += sum(norm * B1[src])            (layer 1)
// POOL=true : sums[batch[node]] += lrelu(AGG + b2)       (layer 2, fused pool)
template <bool POOL>
__global__ __launch_bounds__(256)
void agg_kernel(const int* __restrict__ batch, const float* __restrict__ b2)
{
    int node = (blockIdx.x * blockDim.x + threadIdx.x) >> 5;
    int lane = threadIdx.x & 31;
    if (node >= N_NODES) return;

    int beg = g_off[node];
    int end = g_off[node + 1];

    float a0x = 0.f, a0y = 0.f, a0z = 0.f, a0w = 0.f;
    float a1x = 0.f, a1y = 0.f, a1z = 0.f, a1w = 0.f;

    int i = beg;
    for (; i + 2 <= end; i += 2) {
        int2 e0 = g_edge[i];
        int2 e1 = g_edge[i + 1];
        float n0 = __int_as_float(e0.y);
        float n1 = __int_as_float(e1.y);
        uint2 u0 = *(const uint2*)(g_B1h + (size_t)e0.x * C + lane * 4);
        uint2 u1 = *(const uint2*)(g_B1h + (size_t)e1.x * C + lane * 4);
        float2 f0a = __half22float2(*(__half2*)&u0.x);
        float2 f0b = __half22float2(*(__half2*)&u0.y);
        float2 f1a = __half22float2(*(__half2*)&u1.x);
        float2 f1b = __half22float2(*(__half2*)&u1.y);
        a0x += f0a.x * n0; a0y += f0a.y * n0; a0z += f0b.x * n0; a0w += f0b.y * n0;
        a1x += f1a.x * n1; a1y += f1a.y * n1; a1z += f1b.x * n1; a1w += f1b.y * n1;
    }
    if (i < end) {
        int2 e0 = g_edge[i];
        float n0 = __int_as_float(e0.y);
        uint2 u0 = *(const uint2*)(g_B1h + (size_t)e0.x * C + lane * 4);
        float2 f0a = __half22float2(*(__half2*)&u0.x);
        float2 f0b = __half22float2(*(__half2*)&u0.y);
        a0x += f0a.x * n0; a0y += f0a.y * n0; a0z += f0b.x * n0; a0w += f0b.y * n0;
    }

    float* p = g_B2 + (size_t)node * C + lane * 4;   // holds self-loop term
    float4 cur = *(const float4*)p;
    cur.x += a0x + a1x;
    cur.y += a0y + a1y;
    cur.z += a0z + a1z;
    cur.w += a0w + a1w;

    if (!POOL) {
        *(float4*)p = cur;
    } else {
        unsigned g = (unsigned)batch[node];
        if (g >= NG) return;
        float4 b = *(const float4*)(b2 + lane * 4);
        float* q = g_sums + g * C + lane * 4;
        atomicAdd(q + 0, lrelu(cur.x + b.x));
        atomicAdd(q + 1, lrelu(cur.y + b.y));
        atomicAdd(q + 2, lrelu(cur.z + b.z));
        atomicAdd(q + 3, lrelu(cur.w + b.w));
    }
}

// ---------------- MLP head ---------------------------------------------------
__global__ __launch_bounds__(128)
void head_kernel(const float* __restrict__ W3, const float* __restrict__ b3,
                 const float* __restrict__ W4, const float* __restrict__ b4,
                 const float* __restrict__ W5, const float* __restrict__ b5,
                 float* __restrict__ out)
{
    int g = blockIdx.x;
    int t = threadIdx.x;
    __shared__ float gv[128], t1[64], t2[64];

    float inv = 1.0f / fmaxf(g_cnts[g], 1.0f);
    gv[t] = g_sums[g * C + t] * inv;
    __syncthreads();

    if (t < 64) {
        float s = b3[t];
#pragma unroll 8
        for (int k = 0; k < 128; k++) s += gv[k] * W3[k * 64 + t];
        t1[t] = lrelu(s);
    }
    __syncthreads();
    if (t < 64) {
        float s = b4[t];
#pragma unroll 8
        for (int k = 0; k < 64; k++) s += t1[k] * W4[k * 64 + t];
        t2[t] = lrelu(s);
    }
    __syncthreads();
    if (t < 10) {
        float s = b5[t];
#pragma unroll 8
        for (int k = 0; k < 64; k++) s += t2[k] * W5[k * 10 + t];
        out[g * 10 + t] = s;
    }
}

// ---------------- launch ----------------------------------------------------
// Inputs resolved by ELEMENT COUNT (ordering-agnostic). edge_index/batch are
// int32 (JAX x64 disabled downcasts int64 -> int32).
extern "C" void kernel_launch(void* const* d_in, const int* in_sizes, int n_in,
                              void* d_out, int out_size)
{
    const float* x = nullptr;
    const int* ei = nullptr;
    const int* batch = nullptr;
    const float *W1 = nullptr, *b1 = nullptr, *W2 = nullptr, *b2 = nullptr;
    const float *W3 = nullptr, *b3 = nullptr, *W4 = nullptr, *b4 = nullptr;
    const float *W5 = nullptr, *b5 = nullptr;

    for (int i = 0; i < n_in; i++) {
        const void* p = d_in[i];
        switch (in_sizes[i]) {
            case 12800000: x = (const float*)p; break;
            case 3200000:  ei = (const int*)p; break;
            case 100000:   batch = (const int*)p; break;
            case 16384:    if (!W1) W1 = (const float*)p; else W2 = (const float*)p; break;
            case 8192:     W3 = (const float*)p; break;
            case 4096:     W4 = (const float*)p; break;
            case 640:      W5 = (const float*)p; break;
            case 128:      if (!b1) b1 = (const float*)p; else b2 = (const float*)p; break;
            case 64:       if (!b3) b3 = (const float*)p; else b4 = (const float*)p; break;
            case 10:       b5 = (const float*)p; break;
            default: break;
        }
    }
    float* out = (float*)d_out;
    (void)out_size;

    static bool attr_done = false;
    if (!attr_done) {
        cudaFuncSetAttribute(gemm_kernel<false>,
                             cudaFuncAttributeMaxDynamicSharedMemorySize, GEMM_SMEM);
        cudaFuncSetAttribute(gemm_kernel<true>,
                             cudaFuncAttributeMaxDynamicSharedMemorySize, GEMM_SMEM);
        attr_done = true;
    }

    // zero accumulators via async memsets (graph-capturable, no allocation)
    void *p_deg = nullptr, *p_sums = nullptr, *p_cnts = nullptr;
    cudaGetSymbolAddress(&p_deg,  g_deg_i);
    cudaGetSymbolAddress(&p_sums, g_sums);
    cudaGetSymbolAddress(&p_cnts, g_cnts);
    cudaMemsetAsync(p_deg,  0, N_NODES * sizeof(int));
    cudaMemsetAsync(p_sums, 0, NG * C * sizeof(float));
    cudaMemsetAsync(p_cnts, 0, NG * sizeof(float));

    // CSR build: histogram -> coalesced 3-step scan -> fill
    deg_kernel<<<(N_EDGES + 255) / 256, 256>>>(ei, batch);
    block_sum_kernel<<<NBLK, 256>>>();
    scan_partials_kernel<<<1, 512>>>();
    csr_emit_kernel<<<NBLK, 256>>>();
    fill_kernel<<<(N_EDGES + 255) / 256, 256>>>(ei);

    const int GEMM_GRID = (N_NODES + 63) / 64;   // 1563

    // layer 1
    gemm_kernel<false><<<GEMM_GRID, 256, GEMM_SMEM>>>(x, W1, nullptr);
    agg_kernel<false><<<(N_NODES * 32 + 255) / 256, 256>>>(batch, b2);

    // layer 2 (pool fused into agg)
    gemm_kernel<true><<<GEMM_GRID, 256, GEMM_SMEM>>>(nullptr, W2, b1);
    agg_kernel<true><<<(N_NODES * 32 + 255) / 256, 256>>>(batch, b2);

    // MLP head
    head_kernel<<<NG, 128>>>(W3, b3, W4, b4, W5, b5, out);
}

// round 16
// speedup vs baseline: 2.2196x; 1.0327x over previous
#include <cuda_runtime.h>
#include <cuda_fp16.h>
#include <mma.h>

using namespace nvcuda;

#define N_NODES 100000
#define N_EDGES 1600000
#define C 128
#define NG 128
#define LSLOPE 0.01f
#define FULL 0xffffffffu
#define NBLK ((N_NODES + 255) / 256)        // 391

#define LDA 144            // smem leading dim (halves)
#define GEMM_SMEM ((64 + 128) * LDA * 2)   // 55296 bytes

// ---------------- scratch (device globals: no allocation allowed) ----------
__device__ __align__(16) __half g_B1h[(size_t)N_NODES * C];  // H fp16 (gathered)
__device__ __align__(16) __half g_B2h[(size_t)N_NODES * C];  // activated layer output fp16
__device__ int   g_deg_i[N_NODES];
__device__ float g_dinv[N_NODES];
__device__ int   g_off[N_NODES + 1];       // CSR offsets (by dst)
__device__ int   g_cursor[N_NODES];        // fill cursors
__device__ int2  g_edge[N_EDGES];          // {src, norm-as-int} per CSR slot
__device__ int   g_psum[NBLK];             // per-block degree sums
__device__ int   g_pbase[NBLK];            // exclusive block bases
__device__ __align__(16) float g_sums[NG * C];
__device__ float g_cnts[NG];

__device__ __forceinline__ float lrelu(float v) { return v > 0.f ? v : LSLOPE * v; }

// ---------------- degree histogram + graph counts ----------------------------
__global__ void deg_kernel(const int* __restrict__ ei, const int* __restrict__ batch) {
    int e = blockIdx.x * blockDim.x + threadIdx.x;
    if (e < N_EDGES) {
        unsigned d = (unsigned)ei[N_EDGES + e];
        if (d < N_NODES) atomicAdd(&g_deg_i[d], 1);
    }
    if (e < N_NODES) {
        unsigned g = (unsigned)batch[e];
        if (g < NG) atomicAdd(&g_cnts[g], 1.0f);
    }
}

// ---------------- CSR build: coalesced 3-step scan ---------------------------
__global__ __launch_bounds__(256)
void block_sum_kernel() {
    int t = threadIdx.x;
    int i = blockIdx.x * 256 + t;
    int d = (i < N_NODES) ? g_deg_i[i] : 0;
#pragma unroll
    for (int off = 16; off; off >>= 1) d += __shfl_down_sync(FULL, d, off);
    __shared__ int ws[8];
    if ((t & 31) == 0) ws[t >> 5] = d;
    __syncthreads();
    if (t == 0) {
        int s = 0;
#pragma unroll
        for (int k = 0; k < 8; k++) s += ws[k];
        g_psum[blockIdx.x] = s;
    }
}

__global__ __launch_bounds__(512)
void scan_partials_kernel() {
    __shared__ int sh[512];
    int t = threadIdx.x;
    int v = (t < NBLK) ? g_psum[t] : 0;
    sh[t] = v;
    __syncthreads();
    for (int off = 1; off < 512; off <<= 1) {
        int u = (t >= off) ? sh[t - off] : 0;
        __syncthreads();
        sh[t] += u;
        __syncthreads();
    }
    if (t < NBLK) g_pbase[t] = sh[t] - v;
    if (t == NBLK - 1) g_off[N_NODES] = sh[t];
}

__global__ __launch_bounds__(256)
void csr_emit_kernel() {
    int t = threadIdx.x;
    int lane = t & 31, w = t >> 5;
    int i = blockIdx.x * 256 + t;
    int d = (i < N_NODES) ? g_deg_i[i] : 0;

    int v = d;
#pragma unroll
    for (int off = 1; off < 32; off <<= 1) {
        int u = __shfl_up_sync(FULL, v, off);
        if (lane >= off) v += u;
    }
    __shared__ int wsum[8];
    if (lane == 31) wsum[w] = v;
    __syncthreads();
    if (t < 8) {
        int s = wsum[t];
#pragma unroll
        for (int off = 1; off < 8; off <<= 1) {
            int u = __shfl_up_sync(0xffu, s, off);
            if (t >= off) s += u;
        }
        wsum[t] = s;
    }
    __syncthreads();

    if (i < N_NODES) {
        int base = g_pbase[blockIdx.x] + (w > 0 ? wsum[w - 1] : 0);
        int excl = base + v - d;
        g_off[i]    = excl;
        g_cursor[i] = excl;
        g_dinv[i]   = rsqrtf((float)d + 1.0f);
    }
}

// ---------------- CSR fill: permute edges by dst, packed {src, norm} ---------
__global__ void fill_kernel(const int* __restrict__ ei) {
    int e = blockIdx.x * blockDim.x + threadIdx.x;
    if (e >= N_EDGES) return;
    unsigned s = (unsigned)ei[e];
    unsigned d = (unsigned)ei[N_EDGES + e];
    if (s >= N_NODES || d >= N_NODES) return;
    int pos = atomicAdd(&g_cursor[d], 1);
    float norm = g_dinv[s] * g_dinv[d];
    g_edge[pos] = make_int2((int)s, __float_as_int(norm));
}

// ---------------- WMMA fp16 GEMM: H = X@W -> B1h (fp16) ----------------------
// TRANSFORM=false: X = external fp32 x (layer 1).
// TRANSFORM=true : X = g_B2h fp16 (already activated) — pure copy staging.
template <bool TRANSFORM>
__global__ __launch_bounds__(256)
void gemm_kernel(const float* __restrict__ Xext, const float* __restrict__ W)
{
    extern __shared__ char smem[];
    half* Xs = (half*)smem;                    // [64][LDA]
    half* Ws = (half*)(smem + 64 * LDA * 2);   // [128][LDA]

    int tid  = threadIdx.x;
    int row0 = blockIdx.x * 64;

    if (!TRANSFORM) {
        // fp32 -> fp16 conversion staging
#pragma unroll
        for (int it = 0; it < 8; it++) {
            int idx = tid + it * 256;          // float4 index 0..2047
            int r   = idx >> 5;
            int c4  = (idx & 31) * 4;
            int grow = min(row0 + r, N_NODES - 1);
            float4 v = *(const float4*)(Xext + (size_t)grow * C + c4);
            half2* p = (half2*)(Xs + r * LDA + c4);
            p[0] = __floats2half2_rn(v.x, v.y);
            p[1] = __floats2half2_rn(v.z, v.w);
        }
    } else {
        // fp16 raw copy staging (activation already applied by agg)
#pragma unroll
        for (int it = 0; it < 4; it++) {
            int idx = tid + it * 256;          // uint4 index 0..1023
            int r   = idx >> 4;                // 16 uint4 per row
            int c8  = (idx & 15) * 8;
            int grow = min(row0 + r, N_NODES - 1);
            uint4 v = *(const uint4*)(g_B2h + (size_t)grow * C + c8);
            *(uint4*)(Xs + r * LDA + c8) = v;
        }
    }
#pragma unroll
    for (int it = 0; it < 16; it++) {
        int idx = tid + it * 256;
        int r   = idx >> 5;
        int c4  = (idx & 31) * 4;
        float4 v = *(const float4*)(W + (size_t)r * C + c4);
        half2* p = (half2*)(Ws + r * LDA + c4);
        p[0] = __floats2half2_rn(v.x, v.y);
        p[1] = __floats2half2_rn(v.z, v.w);
    }
    __syncthreads();

    int wid   = tid >> 5;
    int warpM = wid & 1;
    int warpN = wid >> 1;

    wmma::fragment<wmma::accumulator, 16, 16, 16, float> c[2][2];
#pragma unroll
    for (int i = 0; i < 2; i++)
#pragma unroll
        for (int j = 0; j < 2; j++) wmma::fill_fragment(c[i][j], 0.0f);

#pragma unroll
    for (int k = 0; k < C; k += 16) {
        wmma::fragment<wmma::matrix_a, 16, 16, 16, half, wmma::row_major> a[2];
        wmma::fragment<wmma::matrix_b, 16, 16, 16, half, wmma::row_major> b[2];
        wmma::load_matrix_sync(a[0], Xs + (warpM * 32 + 0)  * LDA + k, LDA);
        wmma::load_matrix_sync(a[1], Xs + (warpM * 32 + 16) * LDA + k, LDA);
        wmma::load_matrix_sync(b[0], Ws + k * LDA + warpN * 32 + 0,  LDA);
        wmma::load_matrix_sync(b[1], Ws + k * LDA + warpN * 32 + 16, LDA);
#pragma unroll
        for (int i = 0; i < 2; i++)
#pragma unroll
            for (int j = 0; j < 2; j++)
                wmma::mma_sync(c[i][j], a[i], b[j], c[i][j]);
    }

    __syncthreads();
    float* Cs = (float*)smem;   // [64][128]
#pragma unroll
    for (int i = 0; i < 2; i++)
#pragma unroll
        for (int j = 0; j < 2; j++)
            wmma::store_matrix_sync(Cs + (warpM * 32 + i * 16) * C + warpN * 32 + j * 16,
                                    c[i][j], C, wmma::mem_row_major);
    __syncthreads();

    // epilogue: fp16 B1h only
#pragma unroll
    for (int it = 0; it < 4; it++) {
        int idx = tid + it * 256;              // uint4 index 0..1023
        int r   = idx >> 4;
        int c8  = (idx & 15) * 8;
        int grow = row0 + r;
        if (grow < N_NODES) {
            float4 h0 = *(const float4*)(Cs + r * C + c8);
            float4 h1 = *(const float4*)(Cs + r * C + c8 + 4);
            __half2 p0 = __floats2half2_rn(h0.x, h0.y);
            __half2 p1 = __floats2half2_rn(h0.z, h0.w);
            __half2 p2 = __floats2half2_rn(h1.x, h1.y);
            __half2 p3 = __floats2half2_rn(h1.z, h1.w);
            uint4 packed;
            packed.x = *(unsigned*)&p0;
            packed.y = *(unsigned*)&p1;
            packed.z = *(unsigned*)&p2;
            packed.w = *(unsigned*)&p3;
            *(uint4*)(g_B1h + (size_t)grow * C + c8) = packed;
        }
    }
}

// ---------------- aggregation: self-loop fused, fp16 gathers ------------------
// Warp per dst node, lane owns 4 channels (uint2 = 4 halves), unroll-2.
// AGG = B1h[node]*dinv^2 + sum_e norm_e * B1h[src_e]; v = lrelu(AGG + bias)
// POOL=false: B2h[node] = fp16(v)                        (layer 1)
// POOL=true : sums[batch[node]] += v                     (layer 2, fused pool)
template <bool POOL>
__global__ __launch_bounds__(256)
void agg_kernel(const int* __restrict__ batch, const float* __restrict__ bias)
{
    int node = (blockIdx.x * blockDim.x + threadIdx.x) >> 5;
    int lane = threadIdx.x & 31;
    if (node >= N_NODES) return;

    int beg = g_off[node];
    int end = g_off[node + 1];

    // self-loop term from own (L2-hot) row
    float d  = g_dinv[node];
    float d2 = d * d;
    uint2 su = *(const uint2*)(g_B1h + (size_t)node * C + lane * 4);
    float2 sa = __half22float2(*(__half2*)&su.x);
    float2 sb = __half22float2(*(__half2*)&su.y);

    float a0x = sa.x * d2, a0y = sa.y * d2, a0z = sb.x * d2, a0w = sb.y * d2;
    float a1x = 0.f, a1y = 0.f, a1z = 0.f, a1w = 0.f;

    int i = beg;
    for (; i + 2 <= end; i += 2) {
        int2 e0 = g_edge[i];
        int2 e1 = g_edge[i + 1];
        float n0 = __int_as_float(e0.y);
        float n1 = __int_as_float(e1.y);
        uint2 u0 = *(const uint2*)(g_B1h + (size_t)e0.x * C + lane * 4);
        uint2 u1 = *(const uint2*)(g_B1h + (size_t)e1.x * C + lane * 4);
        float2 f0a = __half22float2(*(__half2*)&u0.x);
        float2 f0b = __half22float2(*(__half2*)&u0.y);
        float2 f1a = __half22float2(*(__half2*)&u1.x);
        float2 f1b = __half22float2(*(__half2*)&u1.y);
        a0x += f0a.x * n0; a0y += f0a.y * n0; a0z += f0b.x * n0; a0w += f0b.y * n0;
        a1x += f1a.x * n1; a1y += f1a.y * n1; a1z += f1b.x * n1; a1w += f1b.y * n1;
    }
    if (i < end) {
        int2 e0 = g_edge[i];
        float n0 = __int_as_float(e0.y);
        uint2 u0 = *(const uint2*)(g_B1h + (size_t)e0.x * C + lane * 4);
        float2 f0a = __half22float2(*(__half2*)&u0.x);
        float2 f0b = __half22float2(*(__half2*)&u0.y);
        a0x += f0a.x * n0; a0y += f0a.y * n0; a0z += f0b.x * n0; a0w += f0b.y * n0;
    }

    float4 b = *(const float4*)(bias + lane * 4);
    float vx = lrelu(a0x + a1x + b.x);
    float vy = lrelu(a0y + a1y + b.y);
    float vz = lrelu(a0z + a1z + b.z);
    float vw = lrelu(a0w + a1w + b.w);

    if (!POOL) {
        __half2 p0 = __floats2half2_rn(vx, vy);
        __half2 p1 = __floats2half2_rn(vz, vw);
        uint2 packed;
        packed.x = *(unsigned*)&p0;
        packed.y = *(unsigned*)&p1;
        *(uint2*)(g_B2h + (size_t)node * C + lane * 4) = packed;
    } else {
        unsigned g = (unsigned)batch[node];
        if (g >= NG) return;
        float* q = g_sums + g * C + lane * 4;
        atomicAdd(q + 0, vx);
        atomicAdd(q + 1, vy);
        atomicAdd(q + 2, vz);
        atomicAdd(q + 3, vw);
    }
}

// ---------------- MLP head ---------------------------------------------------
__global__ __launch_bounds__(128)
void head_kernel(const float* __restrict__ W3, const float* __restrict__ b3,
                 const float* __restrict__ W4, const float* __restrict__ b4,
                 const float* __restrict__ W5, const float* __restrict__ b5,
                 float* __restrict__ out)
{
    int g = blockIdx.x;
    int t = threadIdx.x;
    __shared__ float gv[128], t1[64], t2[64];

    float inv = 1.0f / fmaxf(g_cnts[g], 1.0f);
    gv[t] = g_sums[g * C + t] * inv;
    __syncthreads();

    if (t < 64) {
        float s = b3[t];
#pragma unroll 8
        for (int k = 0; k < 128; k++) s += gv[k] * W3[k * 64 + t];
        t1[t] = lrelu(s);
    }
    __syncthreads();
    if (t < 64) {
        float s = b4[t];
#pragma unroll 8
        for (int k = 0; k < 64; k++) s += t1[k] * W4[k * 64 + t];
        t2[t] = lrelu(s);
    }
    __syncthreads();
    if (t < 10) {
        float s = b5[t];
#pragma unroll 8
        for (int k = 0; k < 64; k++) s += t2[k] * W5[k * 10 + t];
        out[g * 10 + t] = s;
    }
}

// ---------------- launch ----------------------------------------------------
// Inputs resolved by ELEMENT COUNT (ordering-agnostic). edge_index/batch are
// int32 (JAX x64 disabled downcasts int64 -> int32).
extern "C" void kernel_launch(void* const* d_in, const int* in_sizes, int n_in,
                              void* d_out, int out_size)
{
    const float* x = nullptr;
    const int* ei = nullptr;
    const int* batch = nullptr;
    const float *W1 = nullptr, *b1 = nullptr, *W2 = nullptr, *b2 = nullptr;
    const float *W3 = nullptr, *b3 = nullptr, *W4 = nullptr, *b4 = nullptr;
    const float *W5 = nullptr, *b5 = nullptr;

    for (int i = 0; i < n_in; i++) {
        const void* p = d_in[i];
        switch (in_sizes[i]) {
            case 12800000: x = (const float*)p; break;
            case 3200000:  ei = (const int*)p; break;
            case 100000:   batch = (const int*)p; break;
            case 16384:    if (!W1) W1 = (const float*)p; else W2 = (const float*)p; break;
            case 8192:     W3 = (const float*)p; break;
            case 4096:     W4 = (const float*)p; break;
            case 640:      W5 = (const float*)p; break;
            case 128:      if (!b1) b1 = (const float*)p; else b2 = (const float*)p; break;
            case 64:       if (!b3) b3 = (const float*)p; else b4 = (const float*)p; break;
            case 10:       b5 = (const float*)p; break;
            default: break;
        }
    }
    float* out = (float*)d_out;
    (void)out_size;

    static bool attr_done = false;
    if (!attr_done) {
        cudaFuncSetAttribute(gemm_kernel<false>,
                             cudaFuncAttributeMaxDynamicSharedMemorySize, GEMM_SMEM);
        cudaFuncSetAttribute(gemm_kernel<true>,
                             cudaFuncAttributeMaxDynamicSharedMemorySize, GEMM_SMEM);
        attr_done = true;
    }

    // zero accumulators via async memsets (graph-capturable, no allocation)
    void *p_deg = nullptr, *p_sums = nullptr, *p_cnts = nullptr;
    cudaGetSymbolAddress(&p_deg,  g_deg_i);
    cudaGetSymbolAddress(&p_sums, g_sums);
    cudaGetSymbolAddress(&p_cnts, g_cnts);
    cudaMemsetAsync(p_deg,  0, N_NODES * sizeof(int));
    cudaMemsetAsync(p_sums, 0, NG * C * sizeof(float));
    cudaMemsetAsync(p_cnts, 0, NG * sizeof(float));

    // CSR build: histogram -> coalesced 3-step scan -> fill
    deg_kernel<<<(N_EDGES + 255) / 256, 256>>>(ei, batch);
    block_sum_kernel<<<NBLK, 256>>>();
    scan_partials_kernel<<<1, 512>>>();
    csr_emit_kernel<<<NBLK, 256>>>();
    fill_kernel<<<(N_EDGES + 255) / 256, 256>>>(ei);

    const int GEMM_GRID = (N_NODES + 63) / 64;   // 1563

    // layer 1: B1h = x@W1 ; B2h = lrelu(agg + b1)
    gemm_kernel<false><<<GEMM_GRID, 256, GEMM_SMEM>>>(x, W1);
    agg_kernel<false><<<(N_NODES * 32 + 255) / 256, 256>>>(batch, b1);

    // layer 2: B1h = B2h@W2 ; pool += lrelu(agg + b2)
    gemm_kernel<true><<<GEMM_GRID, 256, GEMM_SMEM>>>(nullptr, W2);
    agg_kernel<true><<<(N_NODES * 32 + 255) / 256, 256>>>(batch, b2);

    // MLP head
    head_kernel<<<NG, 128>>>(W3, b3, W4, b4, W5, b5, out);
}